// round 1
// baseline (speedup 1.0000x reference)
#include <cuda_runtime.h>
#include <math.h>

// Problem constants
#define BB 4
#define HH 8
#define NN 2048
#define DD 512
#define DH 64
// derived
#define M_TOT (BB*NN)          // 8192
#define NQKV (3*DD)            // 1536
#define PER_BH (NN*DH)         // 131072

// ---------------- device scratch (no allocation allowed) ----------------
__device__ float g_qkv[(size_t)3*BB*HH*NN*DH];   // [part][b][h][n][d]  ~50MB
__device__ float g_obuf[(size_t)BB*HH*NN*DH];    // [b][h][n][d]        ~17MB
__device__ float g_xsq[M_TOT];
__device__ float g_wqsq[NQKV];
__device__ float g_wosq[DD];
__device__ float g_osq[M_TOT];

// ---------------- row squared-norms for x, w_qkv, w_out ----------------
__global__ void rownorm_kernel(const float* __restrict__ x,
                               const float* __restrict__ wq,
                               const float* __restrict__ wo) {
    int r = blockIdx.x;
    const float* src;
    float* dst;
    if (r < M_TOT)              { src = x  + (size_t)r * DD;          dst = g_xsq  + r; }
    else if (r < M_TOT + NQKV)  { src = wq + (size_t)(r - M_TOT)*DD;  dst = g_wqsq + (r - M_TOT); }
    else                        { src = wo + (size_t)(r - M_TOT - NQKV)*DD; dst = g_wosq + (r - M_TOT - NQKV); }

    float4 v = ((const float4*)src)[threadIdx.x];   // 128 threads * 4 = 512
    float s = v.x*v.x + v.y*v.y + v.z*v.z + v.w*v.w;
    #pragma unroll
    for (int o = 16; o > 0; o >>= 1) s += __shfl_xor_sync(0xffffffffu, s, o);
    __shared__ float ws[4];
    if ((threadIdx.x & 31) == 0) ws[threadIdx.x >> 5] = s;
    __syncthreads();
    if (threadIdx.x == 0) *dst = ws[0] + ws[1] + ws[2] + ws[3];
}

// ---------------- GEMM1: qkv = cdist(x, w_qkv), scattered to [3][B][H][N][DH] ----------------
// C[m, col] = sqrt(max(xsq[m] + wsq[col] - 2 * x_m . w_col, 0))
// 128x128 tile, BK=16, 256 threads, 8x8 microtile.
__global__ __launch_bounds__(256) void qkv_gemm_kernel(const float* __restrict__ X,
                                                       const float* __restrict__ W) {
    __shared__ float As[16 * 132];
    __shared__ float Bs[16 * 132];
    int tid = threadIdx.x;
    int tx = tid & 15, ty = tid >> 4;
    int n0 = blockIdx.x * 128, m0 = blockIdx.y * 128;

    float acc[8][8];
    #pragma unroll
    for (int r = 0; r < 8; r++)
        #pragma unroll
        for (int c = 0; c < 8; c++) acc[r][c] = 0.f;

    for (int kt = 0; kt < DD; kt += 16) {
        #pragma unroll
        for (int u = 0; u < 2; u++) {
            int idx = tid + 256 * u;
            int row = idx >> 2;
            int kq  = (idx & 3) * 4;
            float4 a = *(const float4*)&X[(size_t)(m0 + row) * DD + kt + kq];
            As[(kq+0)*132 + row] = a.x; As[(kq+1)*132 + row] = a.y;
            As[(kq+2)*132 + row] = a.z; As[(kq+3)*132 + row] = a.w;
            float4 b = *(const float4*)&W[(size_t)(n0 + row) * DD + kt + kq];
            Bs[(kq+0)*132 + row] = b.x; Bs[(kq+1)*132 + row] = b.y;
            Bs[(kq+2)*132 + row] = b.z; Bs[(kq+3)*132 + row] = b.w;
        }
        __syncthreads();
        #pragma unroll
        for (int kk = 0; kk < 16; kk++) {
            float a[8], b[8];
            *(float4*)&a[0] = *(const float4*)&As[kk*132 + 8*ty];
            *(float4*)&a[4] = *(const float4*)&As[kk*132 + 8*ty + 4];
            *(float4*)&b[0] = *(const float4*)&Bs[kk*132 + 8*tx];
            *(float4*)&b[4] = *(const float4*)&Bs[kk*132 + 8*tx + 4];
            #pragma unroll
            for (int r = 0; r < 8; r++)
                #pragma unroll
                for (int c = 0; c < 8; c++) acc[r][c] += a[r] * b[c];
        }
        __syncthreads();
    }

    #pragma unroll
    for (int r = 0; r < 8; r++) {
        int m = m0 + 8*ty + r;
        int b = m >> 11, n = m & 2047;
        float xs = g_xsq[m];
        #pragma unroll
        for (int c = 0; c < 8; c++) {
            int col = n0 + 8*tx + c;
            float val = sqrtf(fmaxf(xs + g_wqsq[col] - 2.f * acc[r][c], 0.f));
            int part = col >> 9, rem = col & 511;
            int h = rem >> 6, d = rem & 63;
            g_qkv[(size_t)(part*32 + b*8 + h) * PER_BH + (size_t)n*64 + d] = val;
        }
    }
}

// ---------------- flash attention (fp32), sim = (2 q.k - |q|^2 - |k|^2) / 8 ----------------
// CTA: 128 query rows x full DH. j-tiles of 64. 256 threads = 16(tx: cols) x 16(ty: rows),
// 8 rows x 4 cols per thread. P staged through smem (transposed) for the PV GEMM.
#define FLASH_SMEM_FLOATS (64*132 + 64*68 + 64*68 + 64*132 + 128 + 64)
__global__ __launch_bounds__(256) void flash_kernel() {
    extern __shared__ float sm[];
    float* Qt    = sm;                 // [64 d][132] (128 rows + pad)
    float* Kt    = Qt + 64*132;        // [64 d][68]  (64 j + pad)
    float* Vs    = Kt + 64*68;         // [64 j][68]  (64 d + pad)
    float* Pt    = Vs + 64*68;         // [64 j][132] (128 rows + pad)
    float* qsq_s = Pt + 64*132;        // [128]
    float* ksq_s = qsq_s + 128;        // [64]

    int tid = threadIdx.x;
    int tx = tid & 15, ty = tid >> 4;
    int bh = blockIdx.y;               // b*8 + h
    int i0 = blockIdx.x * 128;

    const float* qbase = g_qkv + (size_t)(0*32 + bh) * PER_BH + (size_t)i0 * 64;
    const float* kbase = g_qkv + (size_t)(1*32 + bh) * PER_BH;
    const float* vbase = g_qkv + (size_t)(2*32 + bh) * PER_BH;

    // Q tile (128x64) transposed into smem
    #pragma unroll
    for (int u = 0; u < 8; u++) {
        int idx = tid + 256 * u;
        int row = idx >> 4;
        int dq  = (idx & 15) * 4;
        float4 v = *(const float4*)&qbase[(size_t)row * 64 + dq];
        Qt[(dq+0)*132 + row] = v.x; Qt[(dq+1)*132 + row] = v.y;
        Qt[(dq+2)*132 + row] = v.z; Qt[(dq+3)*132 + row] = v.w;
    }
    __syncthreads();
    if (tid < 128) {
        float s = 0.f;
        #pragma unroll 8
        for (int kk = 0; kk < 64; kk++) { float q = Qt[kk*132 + tid]; s += q * q; }
        qsq_s[tid] = s;
    }

    float m_r[8], l_r[8], rowqs[8], acc[8][4];
    __syncthreads();
    #pragma unroll
    for (int r = 0; r < 8; r++) {
        m_r[r] = -1e30f; l_r[r] = 0.f;
        rowqs[r] = qsq_s[8*ty + r];
        #pragma unroll
        for (int c = 0; c < 4; c++) acc[r][c] = 0.f;
    }

    for (int j0 = 0; j0 < NN; j0 += 64) {
        __syncthreads();   // previous PV done before K/V/P overwrite
        #pragma unroll
        for (int u = 0; u < 4; u++) {
            int idx = tid + 256 * u;
            int row = idx >> 4;
            int dq  = (idx & 15) * 4;
            float4 kv = *(const float4*)&kbase[(size_t)(j0 + row) * 64 + dq];
            Kt[(dq+0)*68 + row] = kv.x; Kt[(dq+1)*68 + row] = kv.y;
            Kt[(dq+2)*68 + row] = kv.z; Kt[(dq+3)*68 + row] = kv.w;
            float4 vv = *(const float4*)&vbase[(size_t)(j0 + row) * 64 + dq];
            *(float4*)&Vs[row*68 + dq] = vv;
        }
        __syncthreads();
        if (tid < 64) {
            float s = 0.f;
            #pragma unroll 8
            for (int kk = 0; kk < 64; kk++) { float k = Kt[kk*68 + tid]; s += k * k; }
            ksq_s[tid] = s;
        }
        __syncthreads();

        // S = Q . K^T  (8x4 per thread)
        float s[8][4];
        #pragma unroll
        for (int r = 0; r < 8; r++)
            #pragma unroll
            for (int c = 0; c < 4; c++) s[r][c] = 0.f;
        #pragma unroll 8
        for (int kk = 0; kk < 64; kk++) {
            float a[8], b4[4];
            *(float4*)&a[0]  = *(const float4*)&Qt[kk*132 + 8*ty];
            *(float4*)&a[4]  = *(const float4*)&Qt[kk*132 + 8*ty + 4];
            *(float4*)&b4[0] = *(const float4*)&Kt[kk*68 + 4*tx];
            #pragma unroll
            for (int r = 0; r < 8; r++)
                #pragma unroll
                for (int c = 0; c < 4; c++) s[r][c] += a[r] * b4[c];
        }
        float kqs[4];
        #pragma unroll
        for (int c = 0; c < 4; c++) kqs[c] = ksq_s[4*tx + c];

        // online softmax update
        #pragma unroll
        for (int r = 0; r < 8; r++) {
            float mx = -1e30f;
            #pragma unroll
            for (int c = 0; c < 4; c++) {
                s[r][c] = (2.f * s[r][c] - rowqs[r] - kqs[c]) * 0.125f;
                mx = fmaxf(mx, s[r][c]);
            }
            #pragma unroll
            for (int o = 8; o > 0; o >>= 1) mx = fmaxf(mx, __shfl_xor_sync(0xffffffffu, mx, o));
            float mnew  = fmaxf(m_r[r], mx);
            float alpha = __expf(m_r[r] - mnew);
            float rs = 0.f;
            #pragma unroll
            for (int c = 0; c < 4; c++) {
                float p = __expf(s[r][c] - mnew);
                s[r][c] = p;
                rs += p;
            }
            #pragma unroll
            for (int o = 8; o > 0; o >>= 1) rs += __shfl_xor_sync(0xffffffffu, rs, o);
            l_r[r] = l_r[r] * alpha + rs;
            m_r[r] = mnew;
            #pragma unroll
            for (int c = 0; c < 4; c++) acc[r][c] *= alpha;
            #pragma unroll
            for (int c = 0; c < 4; c++) Pt[(4*tx + c)*132 + 8*ty + r] = s[r][c];
        }
        __syncthreads();

        // O += P . V
        #pragma unroll 8
        for (int kk = 0; kk < 64; kk++) {
            float a[8], b4[4];
            *(float4*)&a[0]  = *(const float4*)&Pt[kk*132 + 8*ty];
            *(float4*)&a[4]  = *(const float4*)&Pt[kk*132 + 8*ty + 4];
            *(float4*)&b4[0] = *(const float4*)&Vs[kk*68 + 4*tx];
            #pragma unroll
            for (int r = 0; r < 8; r++)
                #pragma unroll
                for (int c = 0; c < 4; c++) acc[r][c] += a[r] * b4[c];
        }
    }

    float* obase = g_obuf + (size_t)bh * PER_BH + (size_t)i0 * 64;
    #pragma unroll
    for (int r = 0; r < 8; r++) {
        float inv = 1.f / l_r[r];
        float4 o = make_float4(acc[r][0]*inv, acc[r][1]*inv, acc[r][2]*inv, acc[r][3]*inv);
        *(float4*)&obase[(size_t)(8*ty + r) * 64 + 4*tx] = o;
    }
}

// ---------------- squared norm of attention output rows (in [b,n, h*64+d] order) ----------------
__global__ void osq_kernel() {
    int m = blockIdx.x;
    int b = m >> 11, n = m & 2047;
    int k = threadIdx.x * 4;           // 128 threads * 4 = 512
    int h = k >> 6, d = k & 63;
    float4 v = *(const float4*)&g_obuf[(size_t)(b*8 + h) * PER_BH + (size_t)n*64 + d];
    float s = v.x*v.x + v.y*v.y + v.z*v.z + v.w*v.w;
    #pragma unroll
    for (int o = 16; o > 0; o >>= 1) s += __shfl_xor_sync(0xffffffffu, s, o);
    __shared__ float ws[4];
    if ((threadIdx.x & 31) == 0) ws[threadIdx.x >> 5] = s;
    __syncthreads();
    if (threadIdx.x == 0) g_osq[m] = ws[0] + ws[1] + ws[2] + ws[3];
}

// ---------------- GEMM2: final = cdist(attn_out, w_out) -> d_out [B*N, 512] ----------------
__global__ __launch_bounds__(256) void out_gemm_kernel(const float* __restrict__ W,
                                                       float* __restrict__ out) {
    __shared__ float As[16 * 132];
    __shared__ float Bs[16 * 132];
    int tid = threadIdx.x;
    int tx = tid & 15, ty = tid >> 4;
    int n0 = blockIdx.x * 128, m0 = blockIdx.y * 128;

    float acc[8][8];
    #pragma unroll
    for (int r = 0; r < 8; r++)
        #pragma unroll
        for (int c = 0; c < 8; c++) acc[r][c] = 0.f;

    for (int kt = 0; kt < DD; kt += 16) {
        #pragma unroll
        for (int u = 0; u < 2; u++) {
            int idx = tid + 256 * u;
            int row = idx >> 2;
            int kq  = (idx & 3) * 4;
            int m = m0 + row;
            int b = m >> 11, nn = m & 2047;
            int kg = kt + kq;
            int h = kg >> 6, d = kg & 63;
            float4 a = *(const float4*)&g_obuf[(size_t)(b*8 + h) * PER_BH + (size_t)nn*64 + d];
            As[(kq+0)*132 + row] = a.x; As[(kq+1)*132 + row] = a.y;
            As[(kq+2)*132 + row] = a.z; As[(kq+3)*132 + row] = a.w;
            float4 bv = *(const float4*)&W[(size_t)(n0 + row) * DD + kt + kq];
            Bs[(kq+0)*132 + row] = bv.x; Bs[(kq+1)*132 + row] = bv.y;
            Bs[(kq+2)*132 + row] = bv.z; Bs[(kq+3)*132 + row] = bv.w;
        }
        __syncthreads();
        #pragma unroll
        for (int kk = 0; kk < 16; kk++) {
            float a[8], b[8];
            *(float4*)&a[0] = *(const float4*)&As[kk*132 + 8*ty];
            *(float4*)&a[4] = *(const float4*)&As[kk*132 + 8*ty + 4];
            *(float4*)&b[0] = *(const float4*)&Bs[kk*132 + 8*tx];
            *(float4*)&b[4] = *(const float4*)&Bs[kk*132 + 8*tx + 4];
            #pragma unroll
            for (int r = 0; r < 8; r++)
                #pragma unroll
                for (int c = 0; c < 8; c++) acc[r][c] += a[r] * b[c];
        }
        __syncthreads();
    }

    #pragma unroll
    for (int r = 0; r < 8; r++) {
        int m = m0 + 8*ty + r;
        float os = g_osq[m];
        #pragma unroll
        for (int c = 0; c < 8; c++) {
            int col = n0 + 8*tx + c;
            out[(size_t)m * DD + col] = sqrtf(fmaxf(os + g_wosq[col] - 2.f * acc[r][c], 0.f));
        }
    }
}

// ---------------- launch ----------------
extern "C" void kernel_launch(void* const* d_in, const int* in_sizes, int n_in,
                              void* d_out, int out_size) {
    const float* x    = (const float*)d_in[0];   // [4,2048,512]
    const float* wqkv = (const float*)d_in[1];   // [1536,512]
    const float* wout = (const float*)d_in[2];   // [512,512]
    float* out = (float*)d_out;                  // [4,2048,512]

    const int flash_smem = FLASH_SMEM_FLOATS * (int)sizeof(float);   // ~103 KB
    cudaFuncSetAttribute(flash_kernel, cudaFuncAttributeMaxDynamicSharedMemorySize, flash_smem);

    rownorm_kernel<<<M_TOT + NQKV + DD, 128>>>(x, wqkv, wout);
    qkv_gemm_kernel<<<dim3(NQKV/128, M_TOT/128), 256>>>(x, wqkv);
    flash_kernel<<<dim3(NN/128, BB*HH), 256, flash_smem>>>();
    osq_kernel<<<M_TOT, 128>>>();
    out_gemm_kernel<<<dim3(DD/128, M_TOT/128), 256>>>(wout, out);
}

// round 2
// speedup vs baseline: 3.5966x; 3.5966x over previous
#include <cuda_runtime.h>
#include <cuda_bf16.h>
#include <math.h>
#include <stdint.h>

#define BB 4
#define HH 8
#define NN 2048
#define DD 512
#define DH 64
#define M_TOT (BB*NN)          // 8192
#define NQKV (3*DD)            // 1536
#define LOG2E 1.4426950408889634f

// ---------------- device scratch ----------------
__device__ __align__(16) __nv_bfloat16 g_xb [(size_t)M_TOT*DD];
__device__ __align__(16) __nv_bfloat16 g_wqb[(size_t)NQKV*DD];
__device__ __align__(16) __nv_bfloat16 g_wob[(size_t)DD*DD];
__device__ __align__(16) __nv_bfloat16 g_qkvb[(size_t)3*32*NN*DH];  // centered q,k,v
__device__ __align__(16) __nv_bfloat16 g_ob[(size_t)M_TOT*DD];      // centered attn out
__device__ float g_xsq[M_TOT];
__device__ float g_wqsq[NQKV];
__device__ float g_wosq[DD];
__device__ float g_wrs[DD];     // row-sums of w_out
__device__ float g_osq[M_TOT];

// ---------------- helpers ----------------
__device__ __forceinline__ float fast_exp2(float x){
    float y; asm("ex2.approx.f32 %0, %1;" : "=f"(y) : "f"(x)); return y;
}
__device__ __forceinline__ uint32_t pack_bf2(float lo, float hi){
    uint32_t u; asm("cvt.rn.bf16x2.f32 %0, %1, %2;" : "=r"(u) : "f"(hi), "f"(lo)); return u;
}
__device__ __forceinline__ void ldmx4(uint32_t& r0,uint32_t& r1,uint32_t& r2,uint32_t& r3, const void* p){
    uint32_t a = (uint32_t)__cvta_generic_to_shared(p);
    asm volatile("ldmatrix.sync.aligned.m8n8.x4.shared.b16 {%0,%1,%2,%3}, [%4];"
        : "=r"(r0),"=r"(r1),"=r"(r2),"=r"(r3) : "r"(a));
}
__device__ __forceinline__ void ldmx4t(uint32_t& r0,uint32_t& r1,uint32_t& r2,uint32_t& r3, const void* p){
    uint32_t a = (uint32_t)__cvta_generic_to_shared(p);
    asm volatile("ldmatrix.sync.aligned.m8n8.x4.trans.shared.b16 {%0,%1,%2,%3}, [%4];"
        : "=r"(r0),"=r"(r1),"=r"(r2),"=r"(r3) : "r"(a));
}
__device__ __forceinline__ void mma16816(float* c, uint32_t a0,uint32_t a1,uint32_t a2,uint32_t a3,
                                         uint32_t b0,uint32_t b1){
    asm volatile("mma.sync.aligned.m16n8k16.row.col.f32.bf16.bf16.f32 "
        "{%0,%1,%2,%3}, {%4,%5,%6,%7}, {%8,%9}, {%0,%1,%2,%3};"
        : "+f"(c[0]),"+f"(c[1]),"+f"(c[2]),"+f"(c[3])
        : "r"(a0),"r"(a1),"r"(a2),"r"(a3),"r"(b0),"r"(b1));
}

// ---------------- prep: bf16 convert + row norms (+ row sums for w_out) ----------------
__global__ void prep_kernel(const float* __restrict__ x, const float* __restrict__ wq,
                            const float* __restrict__ wo){
    int r = blockIdx.x;
    const float* src; __nv_bfloat16* dstb; float* dsq; float* drs = nullptr;
    if (r < M_TOT)              { src = x  + (size_t)r*DD; dstb = g_xb  + (size_t)r*DD; dsq = g_xsq + r; }
    else if (r < M_TOT + NQKV)  { int rr = r - M_TOT; src = wq + (size_t)rr*DD; dstb = g_wqb + (size_t)rr*DD; dsq = g_wqsq + rr; }
    else { int rr = r - M_TOT - NQKV; src = wo + (size_t)rr*DD; dstb = g_wob + (size_t)rr*DD; dsq = g_wosq + rr; drs = g_wrs + rr; }

    float4 v = ((const float4*)src)[threadIdx.x];    // 128 thr * 4 = 512
    __nv_bfloat16 b0=__float2bfloat16(v.x), b1=__float2bfloat16(v.y);
    __nv_bfloat16 b2=__float2bfloat16(v.z), b3=__float2bfloat16(v.w);
    __nv_bfloat162 h0; h0.x=b0; h0.y=b1;
    __nv_bfloat162 h1; h1.x=b2; h1.y=b3;
    __nv_bfloat162* d2 = (__nv_bfloat162*)(dstb + threadIdx.x*4);
    d2[0]=h0; d2[1]=h1;
    float f0=__bfloat162float(b0), f1=__bfloat162float(b1);
    float f2=__bfloat162float(b2), f3=__bfloat162float(b3);
    float ss = f0*f0 + f1*f1 + f2*f2 + f3*f3;
    float rs = f0 + f1 + f2 + f3;
    #pragma unroll
    for (int o=16;o>0;o>>=1){ ss += __shfl_xor_sync(~0u, ss, o); rs += __shfl_xor_sync(~0u, rs, o); }
    __shared__ float wsum[4], wsum2[4];
    if ((threadIdx.x&31)==0){ wsum[threadIdx.x>>5]=ss; wsum2[threadIdx.x>>5]=rs; }
    __syncthreads();
    if (threadIdx.x==0){
        *dsq = wsum[0]+wsum[1]+wsum[2]+wsum[3];
        if (drs) *drs = wsum2[0]+wsum2[1]+wsum2[2]+wsum2[3];
    }
}

// ---------------- QKV GEMM (bf16 TC): cdist epilogue, centered scatter ----------------
__global__ __launch_bounds__(256) void qkv_gemm_tc(){
    __shared__ __nv_bfloat16 As[128*72];
    __shared__ __nv_bfloat16 Bs[128*72];
    int tid=threadIdx.x, lane=tid&31, wid=tid>>5;
    int wr=wid>>1, wc=wid&1;
    int m0=blockIdx.y*128, n0=blockIdx.x*128;
    float acc[2][8][4];
    #pragma unroll
    for(int i=0;i<2;i++) for(int j=0;j<8;j++) for(int k=0;k<4;k++) acc[i][j][k]=0.f;

    for (int kt=0; kt<DD; kt+=64){
        __syncthreads();
        #pragma unroll
        for (int u=0;u<4;u++){
            int idx=tid+256*u; int row=idx>>3; int q=idx&7;
            *(uint4*)&As[row*72+q*8] = *(const uint4*)&g_xb [(size_t)(m0+row)*DD + kt + q*8];
            *(uint4*)&Bs[row*72+q*8] = *(const uint4*)&g_wqb[(size_t)(n0+row)*DD + kt + q*8];
        }
        __syncthreads();
        #pragma unroll
        for (int kc=0;kc<4;kc++){
            uint32_t a[2][4];
            #pragma unroll
            for (int mt=0;mt<2;mt++)
                ldmx4(a[mt][0],a[mt][1],a[mt][2],a[mt][3],
                      &As[(wr*32+mt*16+(lane&15))*72 + kc*16 + (lane>>4)*8]);
            #pragma unroll
            for (int p=0;p<4;p++){
                uint32_t b0,b1,b2,b3;
                ldmx4(b0,b1,b2,b3,
                      &Bs[(wc*64+p*16+(lane>>4)*8+(lane&7))*72 + kc*16 + ((lane>>3)&1)*8]);
                #pragma unroll
                for (int mt=0;mt<2;mt++){
                    mma16816(acc[mt][2*p],   a[mt][0],a[mt][1],a[mt][2],a[mt][3], b0,b1);
                    mma16816(acc[mt][2*p+1], a[mt][0],a[mt][1],a[mt][2],a[mt][3], b2,b3);
                }
            }
        }
    }
    #pragma unroll
    for (int mt=0;mt<2;mt++){
        #pragma unroll
        for (int hh=0;hh<2;hh++){
            int m = m0 + wr*32 + mt*16 + (lane>>2) + 8*hh;
            int b = m>>11, n = m&2047;
            float xs = g_xsq[m];
            #pragma unroll
            for (int nt=0;nt<8;nt++){
                int col = n0 + wc*64 + nt*8 + 2*(lane&3);
                float d0 = acc[mt][nt][2*hh], d1 = acc[mt][nt][2*hh+1];
                float v0 = sqrtf(fmaxf(xs + g_wqsq[col]   - 2.f*d0, 0.f)) - 32.f;
                float v1 = sqrtf(fmaxf(xs + g_wqsq[col+1] - 2.f*d1, 0.f)) - 32.f;
                int part = col>>9, rem = col&511, h = rem>>6, d = rem&63;
                __nv_bfloat162 h2; h2.x=__float2bfloat16(v0); h2.y=__float2bfloat16(v1);
                *(__nv_bfloat162*)&g_qkvb[((size_t)(part*32 + b*8 + h)*NN + n)*DH + d] = h2;
            }
        }
    }
}

// ---------------- flash attention (bf16 TC) ----------------
#define FSM_BYTES (18432*3 + 1024)
__global__ __launch_bounds__(256) void flash_tc(){
    extern __shared__ char smem[];
    __nv_bfloat16* Qs = (__nv_bfloat16*)smem;              // [128][72]
    __nv_bfloat16* Ks = (__nv_bfloat16*)(smem + 18432);    // [128][72]
    __nv_bfloat16* Vs = (__nv_bfloat16*)(smem + 36864);    // [128][72]
    float* qsqs = (float*)(smem + 55296);                  // [128]
    float* ksqs = (float*)(smem + 55808);                  // [128]

    int tid=threadIdx.x, lane=tid&31, wid=tid>>5;
    int wr=wid>>1, wc=wid&1;
    int bh = blockIdx.y; int i0 = blockIdx.x*128;
    const __nv_bfloat16* qg = g_qkvb + ((size_t)(0*32+bh)*NN + i0)*DH;
    const __nv_bfloat16* kg = g_qkvb + (size_t)(1*32+bh)*NN*DH;
    const __nv_bfloat16* vg = g_qkvb + (size_t)(2*32+bh)*NN*DH;

    #pragma unroll
    for (int u=0;u<4;u++){
        int idx=tid+256*u; int row=idx>>3; int q=idx&7;
        *(uint4*)&Qs[row*72+q*8] = *(const uint4*)&qg[(size_t)row*DH + q*8];
    }
    __syncthreads();
    if (tid<128){
        const __nv_bfloat162* p=(const __nv_bfloat162*)&Qs[tid*72];
        float s=0.f;
        #pragma unroll
        for(int i=0;i<32;i++){ float2 f=__bfloat1622float2(p[i]); s += f.x*f.x + f.y*f.y; }
        qsqs[tid]=s;
    }
    __syncthreads();
    float rq[2][2];
    #pragma unroll
    for(int mt=0;mt<2;mt++)
        #pragma unroll
        for(int hh=0;hh<2;hh++) rq[mt][hh]=qsqs[wr*32+mt*16+(lane>>2)+8*hh];

    float mr[2][2], lr[2][2], accO[2][8][4];
    #pragma unroll
    for(int i=0;i<2;i++) for(int j=0;j<2;j++){ mr[i][j]=-1e30f; lr[i][j]=0.f; }
    #pragma unroll
    for(int i=0;i<2;i++) for(int j=0;j<8;j++) for(int k=0;k<4;k++) accO[i][j][k]=0.f;

    const float C1 = 0.25f*LOG2E, C2 = 0.125f*LOG2E;

    for (int j0=0; j0<NN; j0+=128){
        __syncthreads();
        #pragma unroll
        for (int u=0;u<4;u++){
            int idx=tid+256*u; int row=idx>>3; int q=idx&7;
            *(uint4*)&Ks[row*72+q*8] = *(const uint4*)&kg[(size_t)(j0+row)*DH+q*8];
            *(uint4*)&Vs[row*72+q*8] = *(const uint4*)&vg[(size_t)(j0+row)*DH+q*8];
        }
        __syncthreads();
        if (tid<128){
            const __nv_bfloat162* p=(const __nv_bfloat162*)&Ks[tid*72];
            float s=0.f;
            #pragma unroll
            for(int i=0;i<32;i++){ float2 f=__bfloat1622float2(p[i]); s+=f.x*f.x+f.y*f.y; }
            ksqs[tid]=s;
        }
        __syncthreads();

        float s[2][8][4];
        #pragma unroll
        for(int i=0;i<2;i++) for(int j=0;j<8;j++) for(int k=0;k<4;k++) s[i][j][k]=0.f;
        #pragma unroll
        for (int kc=0;kc<4;kc++){
            uint32_t a[2][4];
            #pragma unroll
            for (int mt=0;mt<2;mt++)
                ldmx4(a[mt][0],a[mt][1],a[mt][2],a[mt][3],
                      &Qs[(wr*32+mt*16+(lane&15))*72 + kc*16 + (lane>>4)*8]);
            #pragma unroll
            for (int p=0;p<4;p++){
                uint32_t b0,b1,b2,b3;
                ldmx4(b0,b1,b2,b3,
                      &Ks[(wc*64+p*16+(lane>>4)*8+(lane&7))*72 + kc*16 + ((lane>>3)&1)*8]);
                #pragma unroll
                for (int mt=0;mt<2;mt++){
                    mma16816(s[mt][2*p],   a[mt][0],a[mt][1],a[mt][2],a[mt][3], b0,b1);
                    mma16816(s[mt][2*p+1], a[mt][0],a[mt][1],a[mt][2],a[mt][3], b2,b3);
                }
            }
        }

        float kq[8][2];
        #pragma unroll
        for (int nt=0;nt<8;nt++){
            int col = wc*64+nt*8+2*(lane&3);
            kq[nt][0]=ksqs[col]; kq[nt][1]=ksqs[col+1];
        }

        #pragma unroll
        for (int mt=0;mt<2;mt++)
        #pragma unroll
        for (int hh=0;hh<2;hh++){
            float mx=-1e30f;
            #pragma unroll
            for (int nt=0;nt<8;nt++){
                float t0 = C1*s[mt][nt][2*hh]   - C2*(rq[mt][hh]+kq[nt][0]);
                float t1 = C1*s[mt][nt][2*hh+1] - C2*(rq[mt][hh]+kq[nt][1]);
                s[mt][nt][2*hh]=t0; s[mt][nt][2*hh+1]=t1;
                mx=fmaxf(mx,fmaxf(t0,t1));
            }
            mx = fmaxf(mx, __shfl_xor_sync(~0u,mx,1));
            mx = fmaxf(mx, __shfl_xor_sync(~0u,mx,2));
            float mnew = fmaxf(mr[mt][hh], mx);
            float alpha = fast_exp2(mr[mt][hh]-mnew);
            float rs=0.f;
            #pragma unroll
            for (int nt=0;nt<8;nt++){
                float p0 = fast_exp2(s[mt][nt][2*hh]-mnew);
                float p1 = fast_exp2(s[mt][nt][2*hh+1]-mnew);
                s[mt][nt][2*hh]=p0; s[mt][nt][2*hh+1]=p1; rs += p0+p1;
            }
            rs += __shfl_xor_sync(~0u,rs,1);
            rs += __shfl_xor_sync(~0u,rs,2);
            lr[mt][hh] = lr[mt][hh]*alpha + rs;
            mr[mt][hh] = mnew;
            #pragma unroll
            for (int nt=0;nt<8;nt++){ accO[mt][nt][2*hh]*=alpha; accO[mt][nt][2*hh+1]*=alpha; }
        }

        #pragma unroll
        for (int kc=0;kc<4;kc++){
            uint32_t pa[2][4];
            #pragma unroll
            for (int mt=0;mt<2;mt++){
                pa[mt][0]=pack_bf2(s[mt][2*kc][0],   s[mt][2*kc][1]);
                pa[mt][1]=pack_bf2(s[mt][2*kc][2],   s[mt][2*kc][3]);
                pa[mt][2]=pack_bf2(s[mt][2*kc+1][0], s[mt][2*kc+1][1]);
                pa[mt][3]=pack_bf2(s[mt][2*kc+1][2], s[mt][2*kc+1][3]);
            }
            #pragma unroll
            for (int dp=0;dp<4;dp++){
                uint32_t b0,b1,b2,b3;
                ldmx4t(b0,b1,b2,b3,
                       &Vs[(wc*64+kc*16+((lane>>3)&1)*8+(lane&7))*72 + dp*16 + (lane>>4)*8]);
                #pragma unroll
                for (int mt=0;mt<2;mt++){
                    mma16816(accO[mt][2*dp],   pa[mt][0],pa[mt][1],pa[mt][2],pa[mt][3], b0,b1);
                    mma16816(accO[mt][2*dp+1], pa[mt][0],pa[mt][1],pa[mt][2],pa[mt][3], b2,b3);
                }
            }
        }
    }

    // merge the two j-half warps
    __syncthreads();
    float* sO  = (float*)(smem + 18432);   // [128][68]
    float* sm_ = qsqs; float* sl_ = ksqs;
    if (wc==1){
        #pragma unroll
        for (int mt=0;mt<2;mt++)
        #pragma unroll
        for (int hh=0;hh<2;hh++){
            int row = wr*32+mt*16+(lane>>2)+8*hh;
            if ((lane&3)==0){ sm_[row]=mr[mt][hh]; sl_[row]=lr[mt][hh]; }
            #pragma unroll
            for (int nt=0;nt<8;nt++){
                int col = nt*8+2*(lane&3);
                sO[row*68+col]   = accO[mt][nt][2*hh];
                sO[row*68+col+1] = accO[mt][nt][2*hh+1];
            }
        }
    }
    __syncthreads();
    if (wc==0){
        int b = bh>>3, h = bh&7;
        #pragma unroll
        for (int mt=0;mt<2;mt++)
        #pragma unroll
        for (int hh=0;hh<2;hh++){
            int row = wr*32+mt*16+(lane>>2)+8*hh;
            float m1 = sm_[row], l1 = sl_[row];
            float m0v = mr[mt][hh], l0 = lr[mt][hh];
            float mtot = fmaxf(m0v, m1);
            float f0 = fast_exp2(m0v-mtot), f1 = fast_exp2(m1-mtot);
            float inv = 1.f/(l0*f0 + l1*f1);
            __nv_bfloat16* orow = g_ob + (size_t)(b*NN + i0 + row)*DD + h*DH;
            #pragma unroll
            for (int nt=0;nt<8;nt++){
                int col = nt*8+2*(lane&3);
                float o0 = (accO[mt][nt][2*hh]*f0   + sO[row*68+col]*f1  )*inv;
                float o1 = (accO[mt][nt][2*hh+1]*f0 + sO[row*68+col+1]*f1)*inv;
                __nv_bfloat162 h2; h2.x=__float2bfloat16(o0); h2.y=__float2bfloat16(o1);
                *(__nv_bfloat162*)&orow[col] = h2;
            }
        }
    }
}

// ---------------- osq: ||out||^2 per row from centered bf16 ----------------
__global__ void osq_tc(){
    int m = blockIdx.x;
    const __nv_bfloat162* p = (const __nv_bfloat162*)(g_ob + (size_t)m*DD) + threadIdx.x*2;
    float2 f0 = __bfloat1622float2(p[0]);
    float2 f1 = __bfloat1622float2(p[1]);
    float a=f0.x+32.f, b=f0.y+32.f, c=f1.x+32.f, d=f1.y+32.f;
    float s = a*a + b*b + c*c + d*d;
    #pragma unroll
    for (int o=16;o>0;o>>=1) s += __shfl_xor_sync(~0u, s, o);
    __shared__ float ws[4];
    if ((threadIdx.x&31)==0) ws[threadIdx.x>>5]=s;
    __syncthreads();
    if (threadIdx.x==0) g_osq[m]=ws[0]+ws[1]+ws[2]+ws[3];
}

// ---------------- output GEMM (bf16 TC): cdist epilogue ----------------
__global__ __launch_bounds__(256) void out_gemm_tc(float* __restrict__ out){
    __shared__ __nv_bfloat16 As[128*72];
    __shared__ __nv_bfloat16 Bs[128*72];
    int tid=threadIdx.x, lane=tid&31, wid=tid>>5;
    int wr=wid>>1, wc=wid&1;
    int m0=blockIdx.y*128, n0=blockIdx.x*128;
    float acc[2][8][4];
    #pragma unroll
    for(int i=0;i<2;i++) for(int j=0;j<8;j++) for(int k=0;k<4;k++) acc[i][j][k]=0.f;

    for (int kt=0; kt<DD; kt+=64){
        __syncthreads();
        #pragma unroll
        for (int u=0;u<4;u++){
            int idx=tid+256*u; int row=idx>>3; int q=idx&7;
            *(uint4*)&As[row*72+q*8] = *(const uint4*)&g_ob [(size_t)(m0+row)*DD + kt + q*8];
            *(uint4*)&Bs[row*72+q*8] = *(const uint4*)&g_wob[(size_t)(n0+row)*DD + kt + q*8];
        }
        __syncthreads();
        #pragma unroll
        for (int kc=0;kc<4;kc++){
            uint32_t a[2][4];
            #pragma unroll
            for (int mt=0;mt<2;mt++)
                ldmx4(a[mt][0],a[mt][1],a[mt][2],a[mt][3],
                      &As[(wr*32+mt*16+(lane&15))*72 + kc*16 + (lane>>4)*8]);
            #pragma unroll
            for (int p=0;p<4;p++){
                uint32_t b0,b1,b2,b3;
                ldmx4(b0,b1,b2,b3,
                      &Bs[(wc*64+p*16+(lane>>4)*8+(lane&7))*72 + kc*16 + ((lane>>3)&1)*8]);
                #pragma unroll
                for (int mt=0;mt<2;mt++){
                    mma16816(acc[mt][2*p],   a[mt][0],a[mt][1],a[mt][2],a[mt][3], b0,b1);
                    mma16816(acc[mt][2*p+1], a[mt][0],a[mt][1],a[mt][2],a[mt][3], b2,b3);
                }
            }
        }
    }
    #pragma unroll
    for (int mt=0;mt<2;mt++){
        #pragma unroll
        for (int hh=0;hh<2;hh++){
            int m = m0 + wr*32 + mt*16 + (lane>>2) + 8*hh;
            float os = g_osq[m];
            #pragma unroll
            for (int nt=0;nt<8;nt++){
                int col = n0 + wc*64 + nt*8 + 2*(lane&3);
                float dot0 = acc[mt][nt][2*hh]   + 32.f*g_wrs[col];
                float dot1 = acc[mt][nt][2*hh+1] + 32.f*g_wrs[col+1];
                out[(size_t)m*DD + col]   = sqrtf(fmaxf(os + g_wosq[col]   - 2.f*dot0, 0.f));
                out[(size_t)m*DD + col+1] = sqrtf(fmaxf(os + g_wosq[col+1] - 2.f*dot1, 0.f));
            }
        }
    }
}

// ---------------- launch ----------------
extern "C" void kernel_launch(void* const* d_in, const int* in_sizes, int n_in,
                              void* d_out, int out_size) {
    const float* x    = (const float*)d_in[0];
    const float* wqkv = (const float*)d_in[1];
    const float* wout = (const float*)d_in[2];
    float* out = (float*)d_out;

    cudaFuncSetAttribute(flash_tc, cudaFuncAttributeMaxDynamicSharedMemorySize, FSM_BYTES);

    prep_kernel<<<M_TOT + NQKV + DD, 128>>>(x, wqkv, wout);
    qkv_gemm_tc<<<dim3(NQKV/128, M_TOT/128), 256>>>();
    flash_tc<<<dim3(NN/128, 32), 256, FSM_BYTES>>>();
    osq_tc<<<M_TOT, 128>>>();
    out_gemm_tc<<<dim3(DD/128, M_TOT/128), 256>>>(out);
}

// round 3
// speedup vs baseline: 3.6020x; 1.0015x over previous
#include <cuda_runtime.h>
#include <cuda_bf16.h>
#include <math.h>
#include <stdint.h>

#define BB 4
#define HH 8
#define NN 2048
#define DD 512
#define DH 64
#define M_TOT (BB*NN)          // 8192
#define NQKV (3*DD)            // 1536
#define LOG2E 1.4426950408889634f

// ---------------- device scratch ----------------
__device__ __align__(16) __nv_bfloat16 g_xb [(size_t)M_TOT*DD];
__device__ __align__(16) __nv_bfloat16 g_wqb[(size_t)NQKV*DD];
__device__ __align__(16) __nv_bfloat16 g_wob[(size_t)DD*DD];
__device__ __align__(16) __nv_bfloat16 g_qkvb[(size_t)3*32*NN*DH];  // centered q,k,v
__device__ __align__(16) __nv_bfloat16 g_ob[(size_t)M_TOT*DD];      // centered attn out
__device__ float g_xsq[M_TOT];
__device__ float g_wqsq[NQKV];
__device__ float g_wosq[DD];
__device__ float g_wrs[DD];     // row-sums of w_out
__device__ float g_osq[M_TOT];

// ---------------- helpers ----------------
__device__ __forceinline__ float fast_exp2(float x){
    float y; asm("ex2.approx.f32 %0, %1;" : "=f"(y) : "f"(x)); return y;
}
__device__ __forceinline__ uint32_t pack_bf2(float lo, float hi){
    uint32_t u; asm("cvt.rn.bf16x2.f32 %0, %1, %2;" : "=r"(u) : "f"(hi), "f"(lo)); return u;
}
__device__ __forceinline__ void ldmx4(uint32_t& r0,uint32_t& r1,uint32_t& r2,uint32_t& r3, const void* p){
    uint32_t a = (uint32_t)__cvta_generic_to_shared(p);
    asm volatile("ldmatrix.sync.aligned.m8n8.x4.shared.b16 {%0,%1,%2,%3}, [%4];"
        : "=r"(r0),"=r"(r1),"=r"(r2),"=r"(r3) : "r"(a));
}
__device__ __forceinline__ void ldmx4t(uint32_t& r0,uint32_t& r1,uint32_t& r2,uint32_t& r3, const void* p){
    uint32_t a = (uint32_t)__cvta_generic_to_shared(p);
    asm volatile("ldmatrix.sync.aligned.m8n8.x4.trans.shared.b16 {%0,%1,%2,%3}, [%4];"
        : "=r"(r0),"=r"(r1),"=r"(r2),"=r"(r3) : "r"(a));
}
__device__ __forceinline__ void mma16816(float* c, uint32_t a0,uint32_t a1,uint32_t a2,uint32_t a3,
                                         uint32_t b0,uint32_t b1){
    asm volatile("mma.sync.aligned.m16n8k16.row.col.f32.bf16.bf16.f32 "
        "{%0,%1,%2,%3}, {%4,%5,%6,%7}, {%8,%9}, {%0,%1,%2,%3};"
        : "+f"(c[0]),"+f"(c[1]),"+f"(c[2]),"+f"(c[3])
        : "r"(a0),"r"(a1),"r"(a2),"r"(a3),"r"(b0),"r"(b1));
}
__device__ __forceinline__ void cp_async16(void* dst, const void* src){
    uint32_t a = (uint32_t)__cvta_generic_to_shared(dst);
    asm volatile("cp.async.cg.shared.global [%0], [%1], 16;" :: "r"(a), "l"(src) : "memory");
}
#define CP_COMMIT  asm volatile("cp.async.commit_group;" ::: "memory")
#define CP_WAIT1   asm volatile("cp.async.wait_group 1;" ::: "memory")
#define CP_WAIT0   asm volatile("cp.async.wait_group 0;" ::: "memory")

// ---------------- prep: bf16 convert + row norms (+ row sums for w_out, zero osq) ----------------
__global__ void prep_kernel(const float* __restrict__ x, const float* __restrict__ wq,
                            const float* __restrict__ wo){
    int r = blockIdx.x;
    const float* src; __nv_bfloat16* dstb; float* dsq; float* drs = nullptr;
    if (r < M_TOT)              { src = x  + (size_t)r*DD; dstb = g_xb  + (size_t)r*DD; dsq = g_xsq + r; }
    else if (r < M_TOT + NQKV)  { int rr = r - M_TOT; src = wq + (size_t)rr*DD; dstb = g_wqb + (size_t)rr*DD; dsq = g_wqsq + rr; }
    else { int rr = r - M_TOT - NQKV; src = wo + (size_t)rr*DD; dstb = g_wob + (size_t)rr*DD; dsq = g_wosq + rr; drs = g_wrs + rr; }

    float4 v = ((const float4*)src)[threadIdx.x];    // 128 thr * 4 = 512
    __nv_bfloat16 b0=__float2bfloat16(v.x), b1=__float2bfloat16(v.y);
    __nv_bfloat16 b2=__float2bfloat16(v.z), b3=__float2bfloat16(v.w);
    __nv_bfloat162 h0; h0.x=b0; h0.y=b1;
    __nv_bfloat162 h1; h1.x=b2; h1.y=b3;
    __nv_bfloat162* d2 = (__nv_bfloat162*)(dstb + threadIdx.x*4);
    d2[0]=h0; d2[1]=h1;
    float f0=__bfloat162float(b0), f1=__bfloat162float(b1);
    float f2=__bfloat162float(b2), f3=__bfloat162float(b3);
    float ss = f0*f0 + f1*f1 + f2*f2 + f3*f3;
    float rs = f0 + f1 + f2 + f3;
    #pragma unroll
    for (int o=16;o>0;o>>=1){ ss += __shfl_xor_sync(~0u, ss, o); rs += __shfl_xor_sync(~0u, rs, o); }
    __shared__ float wsum[4], wsum2[4];
    if ((threadIdx.x&31)==0){ wsum[threadIdx.x>>5]=ss; wsum2[threadIdx.x>>5]=rs; }
    __syncthreads();
    if (threadIdx.x==0){
        *dsq = wsum[0]+wsum[1]+wsum[2]+wsum[3];
        if (drs) *drs = wsum2[0]+wsum2[1]+wsum2[2]+wsum2[3];
        if (r < M_TOT) g_osq[r] = 0.f;   // zeroed for flash epilogue atomics
    }
}

// ---------------- QKV GEMM (bf16 TC, cp.async double-buffered) ----------------
#define GSM_BYTES (4*18432)
__global__ __launch_bounds__(256) void qkv_gemm_tc(){
    extern __shared__ char smc[];
    __nv_bfloat16* Abuf[2] = { (__nv_bfloat16*)smc,            (__nv_bfloat16*)(smc+36864) };
    __nv_bfloat16* Bbuf[2] = { (__nv_bfloat16*)(smc+18432),    (__nv_bfloat16*)(smc+55296) };
    int tid=threadIdx.x, lane=tid&31, wid=tid>>5;
    int wr=wid>>1, wc=wid&1;
    int m0=blockIdx.y*128, n0=blockIdx.x*128;
    float acc[2][8][4];
    #pragma unroll
    for(int i=0;i<2;i++) for(int j=0;j<8;j++) for(int k=0;k<4;k++) acc[i][j][k]=0.f;

    {   // prologue: stage 0
        #pragma unroll
        for (int u=0;u<4;u++){
            int idx=tid+256*u; int row=idx>>3; int q=idx&7;
            cp_async16(&Abuf[0][row*72+q*8], &g_xb [(size_t)(m0+row)*DD + q*8]);
            cp_async16(&Bbuf[0][row*72+q*8], &g_wqb[(size_t)(n0+row)*DD + q*8]);
        }
        CP_COMMIT;
    }
    int buf=0;
    for (int kt=0; kt<DD; kt+=64, buf^=1){
        if (kt+64 < DD){
            #pragma unroll
            for (int u=0;u<4;u++){
                int idx=tid+256*u; int row=idx>>3; int q=idx&7;
                cp_async16(&Abuf[buf^1][row*72+q*8], &g_xb [(size_t)(m0+row)*DD + kt+64 + q*8]);
                cp_async16(&Bbuf[buf^1][row*72+q*8], &g_wqb[(size_t)(n0+row)*DD + kt+64 + q*8]);
            }
            CP_COMMIT; CP_WAIT1;
        } else CP_WAIT0;
        __syncthreads();
        __nv_bfloat16* As = Abuf[buf]; __nv_bfloat16* Bs = Bbuf[buf];
        #pragma unroll
        for (int kc=0;kc<4;kc++){
            uint32_t a[2][4];
            #pragma unroll
            for (int mt=0;mt<2;mt++)
                ldmx4(a[mt][0],a[mt][1],a[mt][2],a[mt][3],
                      &As[(wr*32+mt*16+(lane&15))*72 + kc*16 + (lane>>4)*8]);
            #pragma unroll
            for (int p=0;p<4;p++){
                uint32_t b0,b1,b2,b3;
                ldmx4(b0,b1,b2,b3,
                      &Bs[(wc*64+p*16+(lane>>4)*8+(lane&7))*72 + kc*16 + ((lane>>3)&1)*8]);
                #pragma unroll
                for (int mt=0;mt<2;mt++){
                    mma16816(acc[mt][2*p],   a[mt][0],a[mt][1],a[mt][2],a[mt][3], b0,b1);
                    mma16816(acc[mt][2*p+1], a[mt][0],a[mt][1],a[mt][2],a[mt][3], b2,b3);
                }
            }
        }
        __syncthreads();
    }
    #pragma unroll
    for (int mt=0;mt<2;mt++){
        #pragma unroll
        for (int hh=0;hh<2;hh++){
            int m = m0 + wr*32 + mt*16 + (lane>>2) + 8*hh;
            int b = m>>11, n = m&2047;
            float xs = g_xsq[m];
            #pragma unroll
            for (int nt=0;nt<8;nt++){
                int col = n0 + wc*64 + nt*8 + 2*(lane&3);
                float d0 = acc[mt][nt][2*hh], d1 = acc[mt][nt][2*hh+1];
                float v0 = sqrtf(fmaxf(xs + g_wqsq[col]   - 2.f*d0, 0.f)) - 32.f;
                float v1 = sqrtf(fmaxf(xs + g_wqsq[col+1] - 2.f*d1, 0.f)) - 32.f;
                int part = col>>9, rem = col&511, h = rem>>6, d = rem&63;
                __nv_bfloat162 h2; h2.x=__float2bfloat16(v0); h2.y=__float2bfloat16(v1);
                *(__nv_bfloat162*)&g_qkvb[((size_t)(part*32 + b*8 + h)*NN + n)*DH + d] = h2;
            }
        }
    }
}

// ---------------- flash attention (bf16 TC, no online max, cp.async, fused osq) ----------------
// smem: Qs 0..18432 | Ks0 18432 | Vs0 36864 | Ks1 55296 | Vs1 73728 | qsqs 92160 | ksqs 92672
#define FSM_BYTES (93184)
__global__ __launch_bounds__(256) void flash_tc(){
    extern __shared__ char smem[];
    __nv_bfloat16* Qs = (__nv_bfloat16*)smem;
    __nv_bfloat16* Kb[2] = { (__nv_bfloat16*)(smem+18432), (__nv_bfloat16*)(smem+55296) };
    __nv_bfloat16* Vb[2] = { (__nv_bfloat16*)(smem+36864), (__nv_bfloat16*)(smem+73728) };
    float* qsqs = (float*)(smem + 92160);
    float* ksqs = (float*)(smem + 92672);

    int tid=threadIdx.x, lane=tid&31, wid=tid>>5;
    int wr=wid>>1, wc=wid&1;
    int bh = blockIdx.y; int i0 = blockIdx.x*128;
    const __nv_bfloat16* qg = g_qkvb + ((size_t)(0*32+bh)*NN + i0)*DH;
    const __nv_bfloat16* kg = g_qkvb + (size_t)(1*32+bh)*NN*DH;
    const __nv_bfloat16* vg = g_qkvb + (size_t)(2*32+bh)*NN*DH;

    // prologue: Q (group), then K/V tile 0 (group)
    #pragma unroll
    for (int u=0;u<4;u++){
        int idx=tid+256*u; int row=idx>>3; int q=idx&7;
        cp_async16(&Qs[row*72+q*8], &qg[(size_t)row*DH + q*8]);
    }
    CP_COMMIT;
    #pragma unroll
    for (int u=0;u<4;u++){
        int idx=tid+256*u; int row=idx>>3; int q=idx&7;
        cp_async16(&Kb[0][row*72+q*8], &kg[(size_t)row*DH + q*8]);
        cp_async16(&Vb[0][row*72+q*8], &vg[(size_t)row*DH + q*8]);
    }
    CP_COMMIT;
    CP_WAIT1;                 // Q ready
    __syncthreads();
    if (tid<128){
        const __nv_bfloat162* p=(const __nv_bfloat162*)&Qs[tid*72];
        float s=0.f;
        #pragma unroll
        for(int i=0;i<32;i++){ float2 f=__bfloat1622float2(p[i]); s += f.x*f.x + f.y*f.y; }
        qsqs[tid]=s;
    }
    __syncthreads();
    float rq[2][2];
    #pragma unroll
    for(int mt=0;mt<2;mt++)
        #pragma unroll
        for(int hh=0;hh<2;hh++) rq[mt][hh]=qsqs[wr*32+mt*16+(lane>>2)+8*hh];

    float lr[2][2], accO[2][8][4];
    #pragma unroll
    for(int i=0;i<2;i++) for(int j=0;j<2;j++) lr[i][j]=0.f;
    #pragma unroll
    for(int i=0;i<2;i++) for(int j=0;j<8;j++) for(int k=0;k<4;k++) accO[i][j][k]=0.f;

    const float C1 = 0.25f*LOG2E, C2 = 0.125f*LOG2E;

    int buf=0;
    for (int j0=0; j0<NN; j0+=128, buf^=1){
        if (j0+128 < NN){
            #pragma unroll
            for (int u=0;u<4;u++){
                int idx=tid+256*u; int row=idx>>3; int q=idx&7;
                cp_async16(&Kb[buf^1][row*72+q*8], &kg[(size_t)(j0+128+row)*DH+q*8]);
                cp_async16(&Vb[buf^1][row*72+q*8], &vg[(size_t)(j0+128+row)*DH+q*8]);
            }
            CP_COMMIT; CP_WAIT1;
        } else CP_WAIT0;
        __syncthreads();
        __nv_bfloat16* Ks = Kb[buf]; __nv_bfloat16* Vs = Vb[buf];

        if (tid<128){
            const __nv_bfloat162* p=(const __nv_bfloat162*)&Ks[tid*72];
            float s=0.f;
            #pragma unroll
            for(int i=0;i<32;i++){ float2 f=__bfloat1622float2(p[i]); s+=f.x*f.x+f.y*f.y; }
            ksqs[tid]=s;
        }

        float s[2][8][4];
        #pragma unroll
        for(int i=0;i<2;i++) for(int j=0;j<8;j++) for(int k=0;k<4;k++) s[i][j][k]=0.f;
        #pragma unroll
        for (int kc=0;kc<4;kc++){
            uint32_t a[2][4];
            #pragma unroll
            for (int mt=0;mt<2;mt++)
                ldmx4(a[mt][0],a[mt][1],a[mt][2],a[mt][3],
                      &Qs[(wr*32+mt*16+(lane&15))*72 + kc*16 + (lane>>4)*8]);
            #pragma unroll
            for (int p=0;p<4;p++){
                uint32_t b0,b1,b2,b3;
                ldmx4(b0,b1,b2,b3,
                      &Ks[(wc*64+p*16+(lane>>4)*8+(lane&7))*72 + kc*16 + ((lane>>3)&1)*8]);
                #pragma unroll
                for (int mt=0;mt<2;mt++){
                    mma16816(s[mt][2*p],   a[mt][0],a[mt][1],a[mt][2],a[mt][3], b0,b1);
                    mma16816(s[mt][2*p+1], a[mt][0],a[mt][1],a[mt][2],a[mt][3], b2,b3);
                }
            }
        }
        __syncthreads();   // ksqs visible (overlapped with the QK MMAs above)

        float kq[8][2];
        #pragma unroll
        for (int nt=0;nt<8;nt++){
            int col = wc*64+nt*8+2*(lane&3);
            kq[nt][0]=ksqs[col]; kq[nt][1]=ksqs[col+1];
        }

        // softmax without max: sim <= 0 always -> exp2 never overflows
        #pragma unroll
        for (int mt=0;mt<2;mt++)
        #pragma unroll
        for (int hh=0;hh<2;hh++){
            float rs=0.f;
            #pragma unroll
            for (int nt=0;nt<8;nt++){
                float p0 = fast_exp2(C1*s[mt][nt][2*hh]   - C2*(rq[mt][hh]+kq[nt][0]));
                float p1 = fast_exp2(C1*s[mt][nt][2*hh+1] - C2*(rq[mt][hh]+kq[nt][1]));
                s[mt][nt][2*hh]=p0; s[mt][nt][2*hh+1]=p1; rs += p0+p1;
            }
            rs += __shfl_xor_sync(~0u,rs,1);
            rs += __shfl_xor_sync(~0u,rs,2);
            lr[mt][hh] += rs;
        }

        #pragma unroll
        for (int kc=0;kc<4;kc++){
            uint32_t pa[2][4];
            #pragma unroll
            for (int mt=0;mt<2;mt++){
                pa[mt][0]=pack_bf2(s[mt][2*kc][0],   s[mt][2*kc][1]);
                pa[mt][1]=pack_bf2(s[mt][2*kc][2],   s[mt][2*kc][3]);
                pa[mt][2]=pack_bf2(s[mt][2*kc+1][0], s[mt][2*kc+1][1]);
                pa[mt][3]=pack_bf2(s[mt][2*kc+1][2], s[mt][2*kc+1][3]);
            }
            #pragma unroll
            for (int dp=0;dp<4;dp++){
                uint32_t b0,b1,b2,b3;
                ldmx4t(b0,b1,b2,b3,
                       &Vs[(wc*64+kc*16+((lane>>3)&1)*8+(lane&7))*72 + dp*16 + (lane>>4)*8]);
                #pragma unroll
                for (int mt=0;mt<2;mt++){
                    mma16816(accO[mt][2*dp],   pa[mt][0],pa[mt][1],pa[mt][2],pa[mt][3], b0,b1);
                    mma16816(accO[mt][2*dp+1], pa[mt][0],pa[mt][1],pa[mt][2],pa[mt][3], b2,b3);
                }
            }
        }
        __syncthreads();
    }

    // merge the two j-half warp groups: plain sums (no max bookkeeping)
    float* sO  = (float*)(smem + 18432);   // [128][68] floats, reuses K/V buffers
    float* sl_ = ksqs;
    if (wc==1){
        #pragma unroll
        for (int mt=0;mt<2;mt++)
        #pragma unroll
        for (int hh=0;hh<2;hh++){
            int row = wr*32+mt*16+(lane>>2)+8*hh;
            if ((lane&3)==0) sl_[row]=lr[mt][hh];
            #pragma unroll
            for (int nt=0;nt<8;nt++){
                int col = nt*8+2*(lane&3);
                sO[row*68+col]   = accO[mt][nt][2*hh];
                sO[row*68+col+1] = accO[mt][nt][2*hh+1];
            }
        }
    }
    __syncthreads();
    if (wc==0){
        int b = bh>>3, h = bh&7;
        #pragma unroll
        for (int mt=0;mt<2;mt++)
        #pragma unroll
        for (int hh=0;hh<2;hh++){
            int row = wr*32+mt*16+(lane>>2)+8*hh;
            float inv = 1.f/(lr[mt][hh] + sl_[row]);
            __nv_bfloat16* orow = g_ob + (size_t)(b*NN + i0 + row)*DD + h*DH;
            float ss = 0.f;
            #pragma unroll
            for (int nt=0;nt<8;nt++){
                int col = nt*8+2*(lane&3);
                float o0 = (accO[mt][nt][2*hh]   + sO[row*68+col]  )*inv;
                float o1 = (accO[mt][nt][2*hh+1] + sO[row*68+col+1])*inv;
                __nv_bfloat162 h2; h2.x=__float2bfloat16(o0); h2.y=__float2bfloat16(o1);
                *(__nv_bfloat162*)&orow[col] = h2;
                float a0=o0+32.f, a1=o1+32.f;
                ss += a0*a0 + a1*a1;
            }
            ss += __shfl_xor_sync(~0u, ss, 1);
            ss += __shfl_xor_sync(~0u, ss, 2);
            if ((lane&3)==0) atomicAdd(&g_osq[b*NN + i0 + row], ss);
        }
    }
}

// ---------------- output GEMM (bf16 TC, cp.async double-buffered) ----------------
__global__ __launch_bounds__(256) void out_gemm_tc(float* __restrict__ out){
    extern __shared__ char smc[];
    __nv_bfloat16* Abuf[2] = { (__nv_bfloat16*)smc,            (__nv_bfloat16*)(smc+36864) };
    __nv_bfloat16* Bbuf[2] = { (__nv_bfloat16*)(smc+18432),    (__nv_bfloat16*)(smc+55296) };
    int tid=threadIdx.x, lane=tid&31, wid=tid>>5;
    int wr=wid>>1, wc=wid&1;
    int m0=blockIdx.y*128, n0=blockIdx.x*128;
    float acc[2][8][4];
    #pragma unroll
    for(int i=0;i<2;i++) for(int j=0;j<8;j++) for(int k=0;k<4;k++) acc[i][j][k]=0.f;

    {
        #pragma unroll
        for (int u=0;u<4;u++){
            int idx=tid+256*u; int row=idx>>3; int q=idx&7;
            cp_async16(&Abuf[0][row*72+q*8], &g_ob [(size_t)(m0+row)*DD + q*8]);
            cp_async16(&Bbuf[0][row*72+q*8], &g_wob[(size_t)(n0+row)*DD + q*8]);
        }
        CP_COMMIT;
    }
    int buf=0;
    for (int kt=0; kt<DD; kt+=64, buf^=1){
        if (kt+64 < DD){
            #pragma unroll
            for (int u=0;u<4;u++){
                int idx=tid+256*u; int row=idx>>3; int q=idx&7;
                cp_async16(&Abuf[buf^1][row*72+q*8], &g_ob [(size_t)(m0+row)*DD + kt+64 + q*8]);
                cp_async16(&Bbuf[buf^1][row*72+q*8], &g_wob[(size_t)(n0+row)*DD + kt+64 + q*8]);
            }
            CP_COMMIT; CP_WAIT1;
        } else CP_WAIT0;
        __syncthreads();
        __nv_bfloat16* As = Abuf[buf]; __nv_bfloat16* Bs = Bbuf[buf];
        #pragma unroll
        for (int kc=0;kc<4;kc++){
            uint32_t a[2][4];
            #pragma unroll
            for (int mt=0;mt<2;mt++)
                ldmx4(a[mt][0],a[mt][1],a[mt][2],a[mt][3],
                      &As[(wr*32+mt*16+(lane&15))*72 + kc*16 + (lane>>4)*8]);
            #pragma unroll
            for (int p=0;p<4;p++){
                uint32_t b0,b1,b2,b3;
                ldmx4(b0,b1,b2,b3,
                      &Bs[(wc*64+p*16+(lane>>4)*8+(lane&7))*72 + kc*16 + ((lane>>3)&1)*8]);
                #pragma unroll
                for (int mt=0;mt<2;mt++){
                    mma16816(acc[mt][2*p],   a[mt][0],a[mt][1],a[mt][2],a[mt][3], b0,b1);
                    mma16816(acc[mt][2*p+1], a[mt][0],a[mt][1],a[mt][2],a[mt][3], b2,b3);
                }
            }
        }
        __syncthreads();
    }
    #pragma unroll
    for (int mt=0;mt<2;mt++){
        #pragma unroll
        for (int hh=0;hh<2;hh++){
            int m = m0 + wr*32 + mt*16 + (lane>>2) + 8*hh;
            float os = g_osq[m];
            #pragma unroll
            for (int nt=0;nt<8;nt++){
                int col = n0 + wc*64 + nt*8 + 2*(lane&3);
                float dot0 = acc[mt][nt][2*hh]   + 32.f*g_wrs[col];
                float dot1 = acc[mt][nt][2*hh+1] + 32.f*g_wrs[col+1];
                out[(size_t)m*DD + col]   = sqrtf(fmaxf(os + g_wosq[col]   - 2.f*dot0, 0.f));
                out[(size_t)m*DD + col+1] = sqrtf(fmaxf(os + g_wosq[col+1] - 2.f*dot1, 0.f));
            }
        }
    }
}

// ---------------- launch ----------------
extern "C" void kernel_launch(void* const* d_in, const int* in_sizes, int n_in,
                              void* d_out, int out_size) {
    const float* x    = (const float*)d_in[0];
    const float* wqkv = (const float*)d_in[1];
    const float* wout = (const float*)d_in[2];
    float* out = (float*)d_out;

    cudaFuncSetAttribute(qkv_gemm_tc, cudaFuncAttributeMaxDynamicSharedMemorySize, GSM_BYTES);
    cudaFuncSetAttribute(out_gemm_tc, cudaFuncAttributeMaxDynamicSharedMemorySize, GSM_BYTES);
    cudaFuncSetAttribute(flash_tc,    cudaFuncAttributeMaxDynamicSharedMemorySize, FSM_BYTES);

    prep_kernel<<<M_TOT + NQKV + DD, 128>>>(x, wqkv, wout);
    qkv_gemm_tc<<<dim3(NQKV/128, M_TOT/128), 256, GSM_BYTES>>>();
    flash_tc<<<dim3(NN/128, 32), 256, FSM_BYTES>>>();
    out_gemm_tc<<<dim3(DD/128, M_TOT/128), 256, GSM_BYTES>>>(out);
}

// round 6
// speedup vs baseline: 6.2909x; 1.7465x over previous
#include <cuda_runtime.h>
#include <cuda_bf16.h>
#include <math.h>
#include <stdint.h>

#define BB 4
#define HH 8
#define NN 2048
#define DD 512
#define DH 64
#define M_TOT (BB*NN)          // 8192
#define NQKV (3*DD)            // 1536
#define LOG2E 1.4426950408889634f

// ---------------- device scratch ----------------
__device__ __align__(16) __nv_bfloat16 g_xb [(size_t)M_TOT*DD];
__device__ __align__(16) __nv_bfloat16 g_wqb[(size_t)NQKV*DD];
__device__ __align__(16) __nv_bfloat16 g_wob[(size_t)DD*DD];
__device__ __align__(16) __nv_bfloat16 g_qkvb[(size_t)3*32*NN*DH];  // centered q,k,v
__device__ __align__(16) __nv_bfloat16 g_ob[(size_t)M_TOT*DD];      // centered attn out
__device__ float g_xsq[M_TOT];
__device__ float g_wqsq[NQKV];
__device__ float g_wosq[DD];
__device__ float g_wrs[DD];                          // row-sums of w_out
__device__ float g_osq[M_TOT];
__device__ __align__(16) float g_qksq[2*32*NN];      // centered |q|^2, |k|^2 per (bh,n)

// ---------------- helpers ----------------
__device__ __forceinline__ float fast_exp2(float x){
    float y; asm("ex2.approx.f32 %0, %1;" : "=f"(y) : "f"(x)); return y;
}
__device__ __forceinline__ uint32_t pack_bf2(float lo, float hi){
    uint32_t u; asm("cvt.rn.bf16x2.f32 %0, %1, %2;" : "=r"(u) : "f"(hi), "f"(lo)); return u;
}
__device__ __forceinline__ void ldmx4(uint32_t& r0,uint32_t& r1,uint32_t& r2,uint32_t& r3, const void* p){
    uint32_t a = (uint32_t)__cvta_generic_to_shared(p);
    asm volatile("ldmatrix.sync.aligned.m8n8.x4.shared.b16 {%0,%1,%2,%3}, [%4];"
        : "=r"(r0),"=r"(r1),"=r"(r2),"=r"(r3) : "r"(a));
}
__device__ __forceinline__ void ldmx4t(uint32_t& r0,uint32_t& r1,uint32_t& r2,uint32_t& r3, const void* p){
    uint32_t a = (uint32_t)__cvta_generic_to_shared(p);
    asm volatile("ldmatrix.sync.aligned.m8n8.x4.trans.shared.b16 {%0,%1,%2,%3}, [%4];"
        : "=r"(r0),"=r"(r1),"=r"(r2),"=r"(r3) : "r"(a));
}
__device__ __forceinline__ void mma16816(float* c, const uint32_t* a,
                                         uint32_t b0,uint32_t b1){
    asm volatile("mma.sync.aligned.m16n8k16.row.col.f32.bf16.bf16.f32 "
        "{%0,%1,%2,%3}, {%4,%5,%6,%7}, {%8,%9}, {%0,%1,%2,%3};"
        : "+f"(c[0]),"+f"(c[1]),"+f"(c[2]),"+f"(c[3])
        : "r"(a[0]),"r"(a[1]),"r"(a[2]),"r"(a[3]),"r"(b0),"r"(b1));
}
__device__ __forceinline__ void cp_async16(void* dst, const void* src){
    uint32_t a = (uint32_t)__cvta_generic_to_shared(dst);
    asm volatile("cp.async.cg.shared.global [%0], [%1], 16;" :: "r"(a), "l"(src) : "memory");
}
#define CP_COMMIT  asm volatile("cp.async.commit_group;" ::: "memory")
template<int N> __device__ __forceinline__ void cp_wait(){
    asm volatile("cp.async.wait_group %0;" :: "n"(N) : "memory");
}

// ---------------- prep: bf16 convert + norms/rowsums, zero accumulators ----------------
__global__ void prep_kernel(const float* __restrict__ x, const float* __restrict__ wq,
                            const float* __restrict__ wo){
    int r = blockIdx.x;
    const float* src; __nv_bfloat16* dstb; float* dsq; float* drs = nullptr;
    if (r < M_TOT)              { src = x  + (size_t)r*DD; dstb = g_xb  + (size_t)r*DD; dsq = g_xsq + r; }
    else if (r < M_TOT + NQKV)  { int rr = r - M_TOT; src = wq + (size_t)rr*DD; dstb = g_wqb + (size_t)rr*DD; dsq = g_wqsq + rr; }
    else { int rr = r - M_TOT - NQKV; src = wo + (size_t)rr*DD; dstb = g_wob + (size_t)rr*DD; dsq = g_wosq + rr; drs = g_wrs + rr; }

    if (r < 1024) g_qksq[r*128 + threadIdx.x] = 0.f;   // zero 2*32*2048 accumulators

    float4 v = ((const float4*)src)[threadIdx.x];
    __nv_bfloat16 b0=__float2bfloat16(v.x), b1=__float2bfloat16(v.y);
    __nv_bfloat16 b2=__float2bfloat16(v.z), b3=__float2bfloat16(v.w);
    __nv_bfloat162 h0; h0.x=b0; h0.y=b1;
    __nv_bfloat162 h1; h1.x=b2; h1.y=b3;
    __nv_bfloat162* d2 = (__nv_bfloat162*)(dstb + threadIdx.x*4);
    d2[0]=h0; d2[1]=h1;
    float f0=__bfloat162float(b0), f1=__bfloat162float(b1);
    float f2=__bfloat162float(b2), f3=__bfloat162float(b3);
    float ss = f0*f0 + f1*f1 + f2*f2 + f3*f3;
    float rs = f0 + f1 + f2 + f3;
    #pragma unroll
    for (int o=16;o>0;o>>=1){ ss += __shfl_xor_sync(~0u, ss, o); rs += __shfl_xor_sync(~0u, rs, o); }
    __shared__ float wsum[4], wsum2[4];
    if ((threadIdx.x&31)==0){ wsum[threadIdx.x>>5]=ss; wsum2[threadIdx.x>>5]=rs; }
    __syncthreads();
    if (threadIdx.x==0){
        *dsq = wsum[0]+wsum[1]+wsum[2]+wsum[3];
        if (drs) *drs = wsum2[0]+wsum2[1]+wsum2[2]+wsum2[3];
        if (r < M_TOT) g_osq[r] = 0.f;
    }
}

// ---------------- QKV GEMM (mma.sync, cp.async 2-stage) + centered scatter + q/k norms ----------------
#define GSM_BYTES (4*18432)
__global__ __launch_bounds__(256) void qkv_gemm_tc(){
    extern __shared__ char smc[];
    __nv_bfloat16* Abuf[2] = { (__nv_bfloat16*)smc,            (__nv_bfloat16*)(smc+36864) };
    __nv_bfloat16* Bbuf[2] = { (__nv_bfloat16*)(smc+18432),    (__nv_bfloat16*)(smc+55296) };
    int tid=threadIdx.x, lane=tid&31, wid=tid>>5;
    int wr=wid>>1, wc=wid&1;
    int m0=blockIdx.y*128, n0=blockIdx.x*128;
    float acc[2][8][4];
    #pragma unroll
    for(int i=0;i<2;i++) for(int j=0;j<8;j++) for(int k=0;k<4;k++) acc[i][j][k]=0.f;

    {
        #pragma unroll
        for (int u=0;u<4;u++){
            int idx=tid+256*u; int row=idx>>3; int q=idx&7;
            cp_async16(&Abuf[0][row*72+q*8], &g_xb [(size_t)(m0+row)*DD + q*8]);
            cp_async16(&Bbuf[0][row*72+q*8], &g_wqb[(size_t)(n0+row)*DD + q*8]);
        }
        CP_COMMIT;
    }
    int buf=0;
    for (int kt=0; kt<DD; kt+=64, buf^=1){
        if (kt+64 < DD){
            #pragma unroll
            for (int u=0;u<4;u++){
                int idx=tid+256*u; int row=idx>>3; int q=idx&7;
                cp_async16(&Abuf[buf^1][row*72+q*8], &g_xb [(size_t)(m0+row)*DD + kt+64 + q*8]);
                cp_async16(&Bbuf[buf^1][row*72+q*8], &g_wqb[(size_t)(n0+row)*DD + kt+64 + q*8]);
            }
            CP_COMMIT; cp_wait<1>();
        } else cp_wait<0>();
        __syncthreads();
        __nv_bfloat16* As = Abuf[buf]; __nv_bfloat16* Bs = Bbuf[buf];
        #pragma unroll
        for (int kc=0;kc<4;kc++){
            uint32_t a[2][4];
            #pragma unroll
            for (int mt=0;mt<2;mt++)
                ldmx4(a[mt][0],a[mt][1],a[mt][2],a[mt][3],
                      &As[(wr*32+mt*16+(lane&15))*72 + kc*16 + (lane>>4)*8]);
            #pragma unroll
            for (int p=0;p<4;p++){
                uint32_t b0,b1,b2,b3;
                ldmx4(b0,b1,b2,b3,
                      &Bs[(wc*64+p*16+(lane>>4)*8+(lane&7))*72 + kc*16 + ((lane>>3)&1)*8]);
                #pragma unroll
                for (int mt=0;mt<2;mt++){
                    mma16816(acc[mt][2*p],   a[mt], b0,b1);
                    mma16816(acc[mt][2*p+1], a[mt], b2,b3);
                }
            }
        }
        __syncthreads();
    }
    int colbase = n0 + wc*64;
    int part = colbase>>9, rem = colbase&511, h = rem>>6;
    #pragma unroll
    for (int mt=0;mt<2;mt++){
        #pragma unroll
        for (int hh=0;hh<2;hh++){
            int m = m0 + wr*32 + mt*16 + (lane>>2) + 8*hh;
            int b = m>>11, n = m&2047;
            float xs = g_xsq[m];
            __nv_bfloat16* orow = g_qkvb + ((size_t)(part*32 + b*8 + h)*NN + n)*DH;
            float ss = 0.f;
            #pragma unroll
            for (int nt=0;nt<8;nt++){
                int col = colbase + nt*8 + 2*(lane&3);
                float d0 = acc[mt][nt][2*hh], d1 = acc[mt][nt][2*hh+1];
                float v0 = sqrtf(fmaxf(xs + g_wqsq[col]   - 2.f*d0, 0.f)) - 32.f;
                float v1 = sqrtf(fmaxf(xs + g_wqsq[col+1] - 2.f*d1, 0.f)) - 32.f;
                __nv_bfloat162 h2; h2.x=__float2bfloat16(v0); h2.y=__float2bfloat16(v1);
                *(__nv_bfloat162*)&orow[nt*8 + 2*(lane&3)] = h2;
                ss += v0*v0 + v1*v1;
            }
            if (part < 2){
                ss += __shfl_xor_sync(~0u, ss, 1);
                ss += __shfl_xor_sync(~0u, ss, 2);
                if ((lane&3)==0) atomicAdd(&g_qksq[(part*32 + b*8 + h)*NN + n], ss);
            }
        }
    }
}

// ---------------- flash attention: warp-private 16 rows, j-tile 64, hoisted Q frags ----------------
// smem: Qs [128][72] 0..18432 | K0 18432 | V0 27648 | K1 36864 | V1 46080 | ksq0 55296 | ksq1 55552
#define FSM_BYTES (55808)
__global__ __launch_bounds__(256,2) void flash_tc(){
    extern __shared__ char smem[];
    __nv_bfloat16* Qs = (__nv_bfloat16*)smem;
    __nv_bfloat16* Kb[2] = { (__nv_bfloat16*)(smem+18432), (__nv_bfloat16*)(smem+36864) };
    __nv_bfloat16* Vb[2] = { (__nv_bfloat16*)(smem+27648), (__nv_bfloat16*)(smem+46080) };
    float* ksqb[2] = { (float*)(smem+55296), (float*)(smem+55552) };

    int tid=threadIdx.x, lane=tid&31, w=tid>>5;
    int bh = blockIdx.y; int i0 = blockIdx.x*128;
    const __nv_bfloat16* qg = g_qkvb + ((size_t)(0*32+bh)*NN + i0)*DH;
    const __nv_bfloat16* kg = g_qkvb + (size_t)(1*32+bh)*NN*DH;
    const __nv_bfloat16* vg = g_qkvb + (size_t)(2*32+bh)*NN*DH;
    const float* qsqg = g_qksq + (size_t)(0*32+bh)*NN + i0;
    const float* ksqg = g_qksq + (size_t)(1*32+bh)*NN;

    // Q tile (group), then K/V/ksq tile 0 (group)
    #pragma unroll
    for (int u=0;u<4;u++){
        int idx=tid+256*u; int row=idx>>3; int q=idx&7;
        cp_async16(&Qs[row*72+q*8], &qg[(size_t)row*DH + q*8]);
    }
    CP_COMMIT;
    #pragma unroll
    for (int u=0;u<2;u++){
        int idx=tid+256*u; int row=idx>>3; int q=idx&7;
        cp_async16(&Kb[0][row*72+q*8], &kg[(size_t)row*DH + q*8]);
        cp_async16(&Vb[0][row*72+q*8], &vg[(size_t)row*DH + q*8]);
    }
    if (tid<16) cp_async16(&ksqb[0][tid*4], &ksqg[tid*4]);
    CP_COMMIT;

    cp_wait<1>();              // Q ready
    __syncthreads();

    // hoist Q fragments: warp w owns rows [16w, 16w+16)
    uint32_t qf[4][4];
    #pragma unroll
    for (int kc=0;kc<4;kc++)
        ldmx4(qf[kc][0],qf[kc][1],qf[kc][2],qf[kc][3],
              &Qs[(w*16+(lane&15))*72 + kc*16 + (lane>>4)*8]);
    float rq[2];
    rq[0] = qsqg[w*16 + (lane>>2)];
    rq[1] = qsqg[w*16 + (lane>>2) + 8];

    float lr[2] = {0.f, 0.f};
    float accO[8][4];
    #pragma unroll
    for (int j=0;j<8;j++) for (int k=0;k<4;k++) accO[j][k]=0.f;

    const float C1 = 0.25f*LOG2E, C2 = 0.125f*LOG2E;

    int buf=0;
    for (int j0=0; j0<NN; j0+=64, buf^=1){
        __syncthreads();       // previous compute on buf^1 finished before overwrite
        if (j0+64 < NN){
            #pragma unroll
            for (int u=0;u<2;u++){
                int idx=tid+256*u; int row=idx>>3; int q=idx&7;
                cp_async16(&Kb[buf^1][row*72+q*8], &kg[(size_t)(j0+64+row)*DH+q*8]);
                cp_async16(&Vb[buf^1][row*72+q*8], &vg[(size_t)(j0+64+row)*DH+q*8]);
            }
            if (tid<16) cp_async16(&ksqb[buf^1][tid*4], &ksqg[j0+64+tid*4]);
            CP_COMMIT; cp_wait<1>();
        } else cp_wait<0>();
        __syncthreads();       // buf loaded & visible
        __nv_bfloat16* Ks = Kb[buf]; __nv_bfloat16* Vs = Vb[buf];
        const float* ksq = ksqb[buf];

        // S = Q.K^T : 16 rows x 64 j per warp
        float s[8][4];
        #pragma unroll
        for(int j=0;j<8;j++) for(int k=0;k<4;k++) s[j][k]=0.f;
        #pragma unroll
        for (int kc=0;kc<4;kc++){
            #pragma unroll
            for (int p=0;p<4;p++){
                uint32_t b0,b1,b2,b3;
                ldmx4(b0,b1,b2,b3,
                      &Ks[(p*16+(lane>>4)*8+(lane&7))*72 + kc*16 + ((lane>>3)&1)*8]);
                mma16816(s[2*p],   qf[kc], b0,b1);
                mma16816(s[2*p+1], qf[kc], b2,b3);
            }
        }

        // softmax without running max (sim <= 0 always)
        #pragma unroll
        for (int hh=0;hh<2;hh++){
            float rs=0.f;
            #pragma unroll
            for (int nt=0;nt<8;nt++){
                int col = nt*8 + 2*(lane&3);
                float p0 = fast_exp2(C1*s[nt][2*hh]   - C2*(rq[hh]+ksq[col]));
                float p1 = fast_exp2(C1*s[nt][2*hh+1] - C2*(rq[hh]+ksq[col+1]));
                s[nt][2*hh]=p0; s[nt][2*hh+1]=p1; rs += p0+p1;
            }
            rs += __shfl_xor_sync(~0u,rs,1);
            rs += __shfl_xor_sync(~0u,rs,2);
            lr[hh] += rs;
        }

        // O += P.V
        #pragma unroll
        for (int kc=0;kc<4;kc++){
            uint32_t pa[4];
            pa[0]=pack_bf2(s[2*kc][0],   s[2*kc][1]);
            pa[1]=pack_bf2(s[2*kc][2],   s[2*kc][3]);
            pa[2]=pack_bf2(s[2*kc+1][0], s[2*kc+1][1]);
            pa[3]=pack_bf2(s[2*kc+1][2], s[2*kc+1][3]);
            #pragma unroll
            for (int dp=0;dp<4;dp++){
                uint32_t b0,b1,b2,b3;
                ldmx4t(b0,b1,b2,b3,
                       &Vs[(kc*16+((lane>>3)&1)*8+(lane&7))*72 + dp*16 + (lane>>4)*8]);
                mma16816(accO[2*dp],   pa, b0,b1);
                mma16816(accO[2*dp+1], pa, b2,b3);
            }
        }
    }

    // epilogue: warp-private rows, no cross-warp merge
    int b = bh>>3, h = bh&7;
    #pragma unroll
    for (int hh=0;hh<2;hh++){
        int row = w*16 + (lane>>2) + 8*hh;
        float inv = 1.f/lr[hh];
        __nv_bfloat16* orow = g_ob + (size_t)(b*NN + i0 + row)*DD + h*DH;
        float ss = 0.f;
        #pragma unroll
        for (int nt=0;nt<8;nt++){
            int col = nt*8 + 2*(lane&3);
            float o0 = accO[nt][2*hh]*inv;
            float o1 = accO[nt][2*hh+1]*inv;
            __nv_bfloat162 h2; h2.x=__float2bfloat16(o0); h2.y=__float2bfloat16(o1);
            *(__nv_bfloat162*)&orow[col] = h2;
            float a0=o0+32.f, a1=o1+32.f;
            ss += a0*a0 + a1*a1;
        }
        ss += __shfl_xor_sync(~0u, ss, 1);
        ss += __shfl_xor_sync(~0u, ss, 2);
        if ((lane&3)==0) atomicAdd(&g_osq[b*NN + i0 + row], ss);
    }
}

// ---------------- output GEMM (mma.sync, cp.async 2-stage) ----------------
__global__ __launch_bounds__(256) void out_gemm_tc(float* __restrict__ out){
    extern __shared__ char smc[];
    __nv_bfloat16* Abuf[2] = { (__nv_bfloat16*)smc,            (__nv_bfloat16*)(smc+36864) };
    __nv_bfloat16* Bbuf[2] = { (__nv_bfloat16*)(smc+18432),    (__nv_bfloat16*)(smc+55296) };
    int tid=threadIdx.x, lane=tid&31, wid=tid>>5;
    int wr=wid>>1, wc=wid&1;
    int m0=blockIdx.y*128, n0=blockIdx.x*128;
    float acc[2][8][4];
    #pragma unroll
    for(int i=0;i<2;i++) for(int j=0;j<8;j++) for(int k=0;k<4;k++) acc[i][j][k]=0.f;

    {
        #pragma unroll
        for (int u=0;u<4;u++){
            int idx=tid+256*u; int row=idx>>3; int q=idx&7;
            cp_async16(&Abuf[0][row*72+q*8], &g_ob [(size_t)(m0+row)*DD + q*8]);
            cp_async16(&Bbuf[0][row*72+q*8], &g_wob[(size_t)(n0+row)*DD + q*8]);
        }
        CP_COMMIT;
    }
    int buf=0;
    for (int kt=0; kt<DD; kt+=64, buf^=1){
        if (kt+64 < DD){
            #pragma unroll
            for (int u=0;u<4;u++){
                int idx=tid+256*u; int row=idx>>3; int q=idx&7;
                cp_async16(&Abuf[buf^1][row*72+q*8], &g_ob [(size_t)(m0+row)*DD + kt+64 + q*8]);
                cp_async16(&Bbuf[buf^1][row*72+q*8], &g_wob[(size_t)(n0+row)*DD + kt+64 + q*8]);
            }
            CP_COMMIT; cp_wait<1>();
        } else cp_wait<0>();
        __syncthreads();
        __nv_bfloat16* As = Abuf[buf]; __nv_bfloat16* Bs = Bbuf[buf];
        #pragma unroll
        for (int kc=0;kc<4;kc++){
            uint32_t a[2][4];
            #pragma unroll
            for (int mt=0;mt<2;mt++)
                ldmx4(a[mt][0],a[mt][1],a[mt][2],a[mt][3],
                      &As[(wr*32+mt*16+(lane&15))*72 + kc*16 + (lane>>4)*8]);
            #pragma unroll
            for (int p=0;p<4;p++){
                uint32_t b0,b1,b2,b3;
                ldmx4(b0,b1,b2,b3,
                      &Bs[(wc*64+p*16+(lane>>4)*8+(lane&7))*72 + kc*16 + ((lane>>3)&1)*8]);
                #pragma unroll
                for (int mt=0;mt<2;mt++){
                    mma16816(acc[mt][2*p],   a[mt], b0,b1);
                    mma16816(acc[mt][2*p+1], a[mt], b2,b3);
                }
            }
        }
        __syncthreads();
    }
    #pragma unroll
    for (int mt=0;mt<2;mt++){
        #pragma unroll
        for (int hh=0;hh<2;hh++){
            int m = m0 + wr*32 + mt*16 + (lane>>2) + 8*hh;
            float os = g_osq[m];
            #pragma unroll
            for (int nt=0;nt<8;nt++){
                int col = n0 + wc*64 + nt*8 + 2*(lane&3);
                float dot0 = acc[mt][nt][2*hh]   + 32.f*g_wrs[col];
                float dot1 = acc[mt][nt][2*hh+1] + 32.f*g_wrs[col+1];
                out[(size_t)m*DD + col]   = sqrtf(fmaxf(os + g_wosq[col]   - 2.f*dot0, 0.f));
                out[(size_t)m*DD + col+1] = sqrtf(fmaxf(os + g_wosq[col+1] - 2.f*dot1, 0.f));
            }
        }
    }
}

// ---------------- launch ----------------
extern "C" void kernel_launch(void* const* d_in, const int* in_sizes, int n_in,
                              void* d_out, int out_size) {
    const float* x    = (const float*)d_in[0];
    const float* wqkv = (const float*)d_in[1];
    const float* wout = (const float*)d_in[2];
    float* out = (float*)d_out;

    cudaFuncSetAttribute(qkv_gemm_tc, cudaFuncAttributeMaxDynamicSharedMemorySize, GSM_BYTES);
    cudaFuncSetAttribute(out_gemm_tc, cudaFuncAttributeMaxDynamicSharedMemorySize, GSM_BYTES);
    cudaFuncSetAttribute(flash_tc,    cudaFuncAttributeMaxDynamicSharedMemorySize, FSM_BYTES);

    prep_kernel<<<M_TOT + NQKV + DD, 128>>>(x, wqkv, wout);
    qkv_gemm_tc<<<dim3(NQKV/128, M_TOT/128), 256, GSM_BYTES>>>();
    flash_tc<<<dim3(NN/128, 32), 256, FSM_BYTES>>>();
    out_gemm_tc<<<dim3(DD/128, M_TOT/128), 256, GSM_BYTES>>>(out);
}

// round 7
// speedup vs baseline: 6.9734x; 1.1085x over previous
#include <cuda_runtime.h>
#include <cuda_bf16.h>
#include <math.h>
#include <stdint.h>

#define BB 4
#define HH 8
#define NN 2048
#define DD 512
#define DH 64
#define M_TOT (BB*NN)          // 8192
#define NQKV (3*DD)            // 1536
#define LOG2E 1.4426950408889634f

// ---------------- device scratch ----------------
__device__ __align__(16) __nv_bfloat16 g_xb [(size_t)M_TOT*DD];
__device__ __align__(16) __nv_bfloat16 g_wqb[(size_t)NQKV*DD];
__device__ __align__(16) __nv_bfloat16 g_wob[(size_t)DD*DD];
__device__ __align__(16) __nv_bfloat16 g_qkvb[(size_t)3*32*NN*DH];  // centered q,k,v
__device__ __align__(16) __nv_bfloat16 g_ob[(size_t)M_TOT*DD];      // centered attn out
__device__ float g_xsq[M_TOT];
__device__ float g_wqsq[NQKV];
__device__ float g_wosq[DD];
__device__ float g_wrs[DD];                          // row-sums of w_out
__device__ float g_osq[M_TOT];
__device__ __align__(16) float g_ksq[32*NN];         // centered |k|^2 per (bh,n)

// ---------------- helpers ----------------
__device__ __forceinline__ float fast_exp2(float x){
    float y; asm("ex2.approx.f32 %0, %1;" : "=f"(y) : "f"(x)); return y;
}
__device__ __forceinline__ uint32_t pack_bf2(float lo, float hi){
    uint32_t u; asm("cvt.rn.bf16x2.f32 %0, %1, %2;" : "=r"(u) : "f"(hi), "f"(lo)); return u;
}
__device__ __forceinline__ void ldmx4(uint32_t& r0,uint32_t& r1,uint32_t& r2,uint32_t& r3, const void* p){
    uint32_t a = (uint32_t)__cvta_generic_to_shared(p);
    asm volatile("ldmatrix.sync.aligned.m8n8.x4.shared.b16 {%0,%1,%2,%3}, [%4];"
        : "=r"(r0),"=r"(r1),"=r"(r2),"=r"(r3) : "r"(a));
}
__device__ __forceinline__ void ldmx4t(uint32_t& r0,uint32_t& r1,uint32_t& r2,uint32_t& r3, const void* p){
    uint32_t a = (uint32_t)__cvta_generic_to_shared(p);
    asm volatile("ldmatrix.sync.aligned.m8n8.x4.trans.shared.b16 {%0,%1,%2,%3}, [%4];"
        : "=r"(r0),"=r"(r1),"=r"(r2),"=r"(r3) : "r"(a));
}
__device__ __forceinline__ void mma16816(float* c, const uint32_t* a,
                                         uint32_t b0,uint32_t b1){
    asm volatile("mma.sync.aligned.m16n8k16.row.col.f32.bf16.bf16.f32 "
        "{%0,%1,%2,%3}, {%4,%5,%6,%7}, {%8,%9}, {%0,%1,%2,%3};"
        : "+f"(c[0]),"+f"(c[1]),"+f"(c[2]),"+f"(c[3])
        : "r"(a[0]),"r"(a[1]),"r"(a[2]),"r"(a[3]),"r"(b0),"r"(b1));
}
__device__ __forceinline__ void cp_async16(void* dst, const void* src){
    uint32_t a = (uint32_t)__cvta_generic_to_shared(dst);
    asm volatile("cp.async.cg.shared.global [%0], [%1], 16;" :: "r"(a), "l"(src) : "memory");
}
#define CP_COMMIT  asm volatile("cp.async.commit_group;" ::: "memory")
template<int N> __device__ __forceinline__ void cp_wait(){
    asm volatile("cp.async.wait_group %0;" :: "n"(N) : "memory");
}

// ---------------- prep: bf16 convert + norms/rowsums, zero accumulators ----------------
__global__ void prep_kernel(const float* __restrict__ x, const float* __restrict__ wq,
                            const float* __restrict__ wo){
    int r = blockIdx.x;
    const float* src; __nv_bfloat16* dstb; float* dsq; float* drs = nullptr;
    if (r < M_TOT)              { src = x  + (size_t)r*DD; dstb = g_xb  + (size_t)r*DD; dsq = g_xsq + r; }
    else if (r < M_TOT + NQKV)  { int rr = r - M_TOT; src = wq + (size_t)rr*DD; dstb = g_wqb + (size_t)rr*DD; dsq = g_wqsq + rr; }
    else { int rr = r - M_TOT - NQKV; src = wo + (size_t)rr*DD; dstb = g_wob + (size_t)rr*DD; dsq = g_wosq + rr; drs = g_wrs + rr; }

    if (r < 512) g_ksq[r*128 + threadIdx.x] = 0.f;   // zero 32*2048 k-norm accumulators

    float4 v = ((const float4*)src)[threadIdx.x];    // 128 thr * 4 = 512
    __nv_bfloat16 b0=__float2bfloat16(v.x), b1=__float2bfloat16(v.y);
    __nv_bfloat16 b2=__float2bfloat16(v.z), b3=__float2bfloat16(v.w);
    __nv_bfloat162 h0; h0.x=b0; h0.y=b1;
    __nv_bfloat162 h1; h1.x=b2; h1.y=b3;
    __nv_bfloat162* d2 = (__nv_bfloat162*)(dstb + threadIdx.x*4);
    d2[0]=h0; d2[1]=h1;
    float f0=__bfloat162float(b0), f1=__bfloat162float(b1);
    float f2=__bfloat162float(b2), f3=__bfloat162float(b3);
    float ss = f0*f0 + f1*f1 + f2*f2 + f3*f3;
    float rs = f0 + f1 + f2 + f3;
    #pragma unroll
    for (int o=16;o>0;o>>=1){ ss += __shfl_xor_sync(~0u, ss, o); rs += __shfl_xor_sync(~0u, rs, o); }
    __shared__ float wsum[4], wsum2[4];
    if ((threadIdx.x&31)==0){ wsum[threadIdx.x>>5]=ss; wsum2[threadIdx.x>>5]=rs; }
    __syncthreads();
    if (threadIdx.x==0){
        *dsq = wsum[0]+wsum[1]+wsum[2]+wsum[3];
        if (drs) *drs = wsum2[0]+wsum2[1]+wsum2[2]+wsum2[3];
        if (r < M_TOT) g_osq[r] = 0.f;
    }
}

// ---------------- QKV GEMM: 3-stage cp.async ring, ONE sync per k-tile ----------------
#define GSM_BYTES (3*36864)
__global__ __launch_bounds__(256) void qkv_gemm_tc(){
    extern __shared__ char smc[];
    int tid=threadIdx.x, lane=tid&31, wid=tid>>5;
    int wr=wid>>1, wc=wid&1;
    int m0=blockIdx.y*128, n0=blockIdx.x*128;
    float acc[2][8][4];
    #pragma unroll
    for(int i=0;i<2;i++) for(int j=0;j<8;j++) for(int k=0;k<4;k++) acc[i][j][k]=0.f;

    auto load_stage = [&](int kt, int st){
        __nv_bfloat16* As = (__nv_bfloat16*)(smc + st*36864);
        __nv_bfloat16* Bs = (__nv_bfloat16*)(smc + st*36864 + 18432);
        #pragma unroll
        for (int u=0;u<4;u++){
            int idx=tid+256*u; int row=idx>>3; int q=idx&7;
            cp_async16(&As[row*72+q*8], &g_xb [(size_t)(m0+row)*DD + kt + q*8]);
            cp_async16(&Bs[row*72+q*8], &g_wqb[(size_t)(n0+row)*DD + kt + q*8]);
        }
    };
    load_stage(0, 0); CP_COMMIT;
    load_stage(64, 1); CP_COMMIT;

    for (int it=0; it<8; it++){
        int st = it%3;
        if (it<7) cp_wait<1>(); else cp_wait<0>();
        __syncthreads();
        if (it+2 < 8){ load_stage((it+2)*64, (it+2)%3); CP_COMMIT; }
        __nv_bfloat16* As = (__nv_bfloat16*)(smc + st*36864);
        __nv_bfloat16* Bs = (__nv_bfloat16*)(smc + st*36864 + 18432);
        #pragma unroll
        for (int kc=0;kc<4;kc++){
            uint32_t a[2][4];
            #pragma unroll
            for (int mt=0;mt<2;mt++)
                ldmx4(a[mt][0],a[mt][1],a[mt][2],a[mt][3],
                      &As[(wr*32+mt*16+(lane&15))*72 + kc*16 + (lane>>4)*8]);
            #pragma unroll
            for (int p=0;p<4;p++){
                uint32_t b0,b1,b2,b3;
                ldmx4(b0,b1,b2,b3,
                      &Bs[(wc*64+p*16+(lane>>4)*8+(lane&7))*72 + kc*16 + ((lane>>3)&1)*8]);
                #pragma unroll
                for (int mt=0;mt<2;mt++){
                    mma16816(acc[mt][2*p],   a[mt], b0,b1);
                    mma16816(acc[mt][2*p+1], a[mt], b2,b3);
                }
            }
        }
    }
    int colbase = n0 + wc*64;
    int part = colbase>>9, rem = colbase&511, h = rem>>6;
    #pragma unroll
    for (int mt=0;mt<2;mt++){
        #pragma unroll
        for (int hh=0;hh<2;hh++){
            int m = m0 + wr*32 + mt*16 + (lane>>2) + 8*hh;
            int b = m>>11, n = m&2047;
            float xs = g_xsq[m];
            __nv_bfloat16* orow = g_qkvb + ((size_t)(part*32 + b*8 + h)*NN + n)*DH;
            float ss = 0.f;
            #pragma unroll
            for (int nt=0;nt<8;nt++){
                int col = colbase + nt*8 + 2*(lane&3);
                float d0 = acc[mt][nt][2*hh], d1 = acc[mt][nt][2*hh+1];
                float v0 = sqrtf(fmaxf(xs + g_wqsq[col]   - 2.f*d0, 0.f)) - 32.f;
                float v1 = sqrtf(fmaxf(xs + g_wqsq[col+1] - 2.f*d1, 0.f)) - 32.f;
                __nv_bfloat162 h2; h2.x=__float2bfloat16(v0); h2.y=__float2bfloat16(v1);
                *(__nv_bfloat162*)&orow[nt*8 + 2*(lane&3)] = h2;
                ss += v0*v0 + v1*v1;
            }
            if (part == 1){   // only k-norms are needed (q-norm cancels in softmax)
                ss += __shfl_xor_sync(~0u, ss, 1);
                ss += __shfl_xor_sync(~0u, ss, 2);
                if ((lane&3)==0) atomicAdd(&g_ksq[(b*8 + h)*NN + n], ss);
            }
        }
    }
}

// ---------------- flash attention: 3-stage ring, ONE sync per j-tile, no q-norm ----------------
// smem: Qs [128][72] = 18432 | stage s at 18432+s*18688: K(9216) V(9216) ksq(256)
#define FSTAGE 18688
#define FSM_BYTES (18432 + 3*FSTAGE)
__global__ __launch_bounds__(256,2) void flash_tc(){
    extern __shared__ char smem[];
    __nv_bfloat16* Qs = (__nv_bfloat16*)smem;

    int tid=threadIdx.x, lane=tid&31, w=tid>>5;
    int bh = blockIdx.y; int i0 = blockIdx.x*128;
    const __nv_bfloat16* qg = g_qkvb + ((size_t)(0*32+bh)*NN + i0)*DH;
    const __nv_bfloat16* kg = g_qkvb + (size_t)(1*32+bh)*NN*DH;
    const __nv_bfloat16* vg = g_qkvb + (size_t)(2*32+bh)*NN*DH;
    const float* ksqg = g_ksq + (size_t)bh*NN;

    auto load_stage = [&](int j0, int st){
        char* base = smem + 18432 + st*FSTAGE;
        __nv_bfloat16* Ks = (__nv_bfloat16*)base;
        __nv_bfloat16* Vs = (__nv_bfloat16*)(base + 9216);
        float* kq = (float*)(base + 18432);
        #pragma unroll
        for (int u=0;u<2;u++){
            int idx=tid+256*u; int row=idx>>3; int q=idx&7;
            cp_async16(&Ks[row*72+q*8], &kg[(size_t)(j0+row)*DH+q*8]);
            cp_async16(&Vs[row*72+q*8], &vg[(size_t)(j0+row)*DH+q*8]);
        }
        if (tid<16) cp_async16(&kq[tid*4], &ksqg[j0+tid*4]);
    };

    // Q (own group), then stage 0, stage 1
    #pragma unroll
    for (int u=0;u<4;u++){
        int idx=tid+256*u; int row=idx>>3; int q=idx&7;
        cp_async16(&Qs[row*72+q*8], &qg[(size_t)row*DH + q*8]);
    }
    CP_COMMIT;
    load_stage(0, 0);  CP_COMMIT;
    load_stage(64, 1); CP_COMMIT;

    cp_wait<2>();             // Q complete
    __syncthreads();

    // hoist Q fragments: warp w owns rows [16w, 16w+16)
    uint32_t qf[4][4];
    #pragma unroll
    for (int kc=0;kc<4;kc++)
        ldmx4(qf[kc][0],qf[kc][1],qf[kc][2],qf[kc][3],
              &Qs[(w*16+(lane&15))*72 + kc*16 + (lane>>4)*8]);

    float lr[2] = {0.f, 0.f};
    float accO[8][4];
    #pragma unroll
    for (int j=0;j<8;j++) for (int k=0;k<4;k++) accO[j][k]=0.f;

    const float C1 = 0.25f*LOG2E, C2 = 0.125f*LOG2E;

    for (int t=0; t<32; t++){
        int st = t%3;
        if (t<31) cp_wait<1>(); else cp_wait<0>();
        __syncthreads();
        if (t+2 < 32){ load_stage((t+2)*64, (t+2)%3); CP_COMMIT; }
        char* base = smem + 18432 + st*FSTAGE;
        __nv_bfloat16* Ks = (__nv_bfloat16*)base;
        __nv_bfloat16* Vs = (__nv_bfloat16*)(base + 9216);
        const float* ksq = (const float*)(base + 18432);

        // S = Q.K^T : 16 rows x 64 j per warp
        float s[8][4];
        #pragma unroll
        for(int j=0;j<8;j++) for(int k=0;k<4;k++) s[j][k]=0.f;
        #pragma unroll
        for (int kc=0;kc<4;kc++){
            #pragma unroll
            for (int p=0;p<4;p++){
                uint32_t b0,b1,b2,b3;
                ldmx4(b0,b1,b2,b3,
                      &Ks[(p*16+(lane>>4)*8+(lane&7))*72 + kc*16 + ((lane>>3)&1)*8]);
                mma16816(s[2*p],   qf[kc], b0,b1);
                mma16816(s[2*p+1], qf[kc], b2,b3);
            }
        }

        // p = exp2(C1*s - C2*|k|^2)  (q-norm term cancels in the softmax ratio)
        #pragma unroll
        for (int hh=0;hh<2;hh++){
            float rs=0.f;
            #pragma unroll
            for (int nt=0;nt<8;nt++){
                int col = nt*8 + 2*(lane&3);
                float p0 = fast_exp2(C1*s[nt][2*hh]   - C2*ksq[col]);
                float p1 = fast_exp2(C1*s[nt][2*hh+1] - C2*ksq[col+1]);
                s[nt][2*hh]=p0; s[nt][2*hh+1]=p1; rs += p0+p1;
            }
            rs += __shfl_xor_sync(~0u,rs,1);
            rs += __shfl_xor_sync(~0u,rs,2);
            lr[hh] += rs;
        }

        // O += P.V
        #pragma unroll
        for (int kc=0;kc<4;kc++){
            uint32_t pa[4];
            pa[0]=pack_bf2(s[2*kc][0],   s[2*kc][1]);
            pa[1]=pack_bf2(s[2*kc][2],   s[2*kc][3]);
            pa[2]=pack_bf2(s[2*kc+1][0], s[2*kc+1][1]);
            pa[3]=pack_bf2(s[2*kc+1][2], s[2*kc+1][3]);
            #pragma unroll
            for (int dp=0;dp<4;dp++){
                uint32_t b0,b1,b2,b3;
                ldmx4t(b0,b1,b2,b3,
                       &Vs[(kc*16+((lane>>3)&1)*8+(lane&7))*72 + dp*16 + (lane>>4)*8]);
                mma16816(accO[2*dp],   pa, b0,b1);
                mma16816(accO[2*dp+1], pa, b2,b3);
            }
        }
    }

    // epilogue: warp-private rows
    int b = bh>>3, h = bh&7;
    #pragma unroll
    for (int hh=0;hh<2;hh++){
        int row = w*16 + (lane>>2) + 8*hh;
        float inv = 1.f/lr[hh];
        __nv_bfloat16* orow = g_ob + (size_t)(b*NN + i0 + row)*DD + h*DH;
        float ss = 0.f;
        #pragma unroll
        for (int nt=0;nt<8;nt++){
            int col = nt*8 + 2*(lane&3);
            float o0 = accO[nt][2*hh]*inv;
            float o1 = accO[nt][2*hh+1]*inv;
            __nv_bfloat162 h2; h2.x=__float2bfloat16(o0); h2.y=__float2bfloat16(o1);
            *(__nv_bfloat162*)&orow[col] = h2;
            float a0=o0+32.f, a1=o1+32.f;
            ss += a0*a0 + a1*a1;
        }
        ss += __shfl_xor_sync(~0u, ss, 1);
        ss += __shfl_xor_sync(~0u, ss, 2);
        if ((lane&3)==0) atomicAdd(&g_osq[b*NN + i0 + row], ss);
    }
}

// ---------------- output GEMM: 3-stage ring, ONE sync per k-tile ----------------
__global__ __launch_bounds__(256) void out_gemm_tc(float* __restrict__ out){
    extern __shared__ char smc[];
    int tid=threadIdx.x, lane=tid&31, wid=tid>>5;
    int wr=wid>>1, wc=wid&1;
    int m0=blockIdx.y*128, n0=blockIdx.x*128;
    float acc[2][8][4];
    #pragma unroll
    for(int i=0;i<2;i++) for(int j=0;j<8;j++) for(int k=0;k<4;k++) acc[i][j][k]=0.f;

    auto load_stage = [&](int kt, int st){
        __nv_bfloat16* As = (__nv_bfloat16*)(smc + st*36864);
        __nv_bfloat16* Bs = (__nv_bfloat16*)(smc + st*36864 + 18432);
        #pragma unroll
        for (int u=0;u<4;u++){
            int idx=tid+256*u; int row=idx>>3; int q=idx&7;
            cp_async16(&As[row*72+q*8], &g_ob [(size_t)(m0+row)*DD + kt + q*8]);
            cp_async16(&Bs[row*72+q*8], &g_wob[(size_t)(n0+row)*DD + kt + q*8]);
        }
    };
    load_stage(0, 0); CP_COMMIT;
    load_stage(64, 1); CP_COMMIT;

    for (int it=0; it<8; it++){
        int st = it%3;
        if (it<7) cp_wait<1>(); else cp_wait<0>();
        __syncthreads();
        if (it+2 < 8){ load_stage((it+2)*64, (it+2)%3); CP_COMMIT; }
        __nv_bfloat16* As = (__nv_bfloat16*)(smc + st*36864);
        __nv_bfloat16* Bs = (__nv_bfloat16*)(smc + st*36864 + 18432);
        #pragma unroll
        for (int kc=0;kc<4;kc++){
            uint32_t a[2][4];
            #pragma unroll
            for (int mt=0;mt<2;mt++)
                ldmx4(a[mt][0],a[mt][1],a[mt][2],a[mt][3],
                      &As[(wr*32+mt*16+(lane&15))*72 + kc*16 + (lane>>4)*8]);
            #pragma unroll
            for (int p=0;p<4;p++){
                uint32_t b0,b1,b2,b3;
                ldmx4(b0,b1,b2,b3,
                      &Bs[(wc*64+p*16+(lane>>4)*8+(lane&7))*72 + kc*16 + ((lane>>3)&1)*8]);
                #pragma unroll
                for (int mt=0;mt<2;mt++){
                    mma16816(acc[mt][2*p],   a[mt], b0,b1);
                    mma16816(acc[mt][2*p+1], a[mt], b2,b3);
                }
            }
        }
    }
    #pragma unroll
    for (int mt=0;mt<2;mt++){
        #pragma unroll
        for (int hh=0;hh<2;hh++){
            int m = m0 + wr*32 + mt*16 + (lane>>2) + 8*hh;
            float os = g_osq[m];
            #pragma unroll
            for (int nt=0;nt<8;nt++){
                int col = n0 + wc*64 + nt*8 + 2*(lane&3);
                float dot0 = acc[mt][nt][2*hh]   + 32.f*g_wrs[col];
                float dot1 = acc[mt][nt][2*hh+1] + 32.f*g_wrs[col+1];
                out[(size_t)m*DD + col]   = sqrtf(fmaxf(os + g_wosq[col]   - 2.f*dot0, 0.f));
                out[(size_t)m*DD + col+1] = sqrtf(fmaxf(os + g_wosq[col+1] - 2.f*dot1, 0.f));
            }
        }
    }
}

// ---------------- launch ----------------
extern "C" void kernel_launch(void* const* d_in, const int* in_sizes, int n_in,
                              void* d_out, int out_size) {
    const float* x    = (const float*)d_in[0];
    const float* wqkv = (const float*)d_in[1];
    const float* wout = (const float*)d_in[2];
    float* out = (float*)d_out;

    cudaFuncSetAttribute(qkv_gemm_tc, cudaFuncAttributeMaxDynamicSharedMemorySize, GSM_BYTES);
    cudaFuncSetAttribute(out_gemm_tc, cudaFuncAttributeMaxDynamicSharedMemorySize, GSM_BYTES);
    cudaFuncSetAttribute(flash_tc,    cudaFuncAttributeMaxDynamicSharedMemorySize, FSM_BYTES);

    prep_kernel<<<M_TOT + NQKV + DD, 128>>>(x, wqkv, wout);
    qkv_gemm_tc<<<dim3(NQKV/128, M_TOT/128), 256, GSM_BYTES>>>();
    flash_tc<<<dim3(NN/128, 32), 256, FSM_BYTES>>>();
    out_gemm_tc<<<dim3(DD/128, M_TOT/128), 256, GSM_BYTES>>>(out);
}

// round 8
// speedup vs baseline: 6.9862x; 1.0018x over previous
#include <cuda_runtime.h>
#include <cuda_bf16.h>
#include <math.h>
#include <stdint.h>

#define BB 4
#define HH 8
#define NN 2048
#define DD 512
#define DH 64
#define M_TOT (BB*NN)          // 8192
#define NQKV (3*DD)            // 1536
#define LOG2E 1.4426950408889634f

// ---------------- device scratch ----------------
__device__ __align__(16) __nv_bfloat16 g_xb [(size_t)M_TOT*DD];
__device__ __align__(16) __nv_bfloat16 g_wqb[(size_t)NQKV*DD];
__device__ __align__(16) __nv_bfloat16 g_wob[(size_t)DD*DD];
__device__ __align__(16) __nv_bfloat16 g_qkvb[(size_t)3*32*NN*DH];  // centered q,k,v
__device__ __align__(16) __nv_bfloat16 g_ob[(size_t)M_TOT*DD];      // centered attn out
__device__ float g_xsq[M_TOT];
__device__ float g_wqsq[NQKV];
__device__ float g_wosq[DD];
__device__ float g_wrs[DD];                          // row-sums of w_out
__device__ float g_osq[M_TOT];
__device__ __align__(16) float g_ksq[32*NN];         // centered |k|^2 per (bh,n)

// ---------------- helpers ----------------
__device__ __forceinline__ float fast_exp2(float x){
    float y; asm("ex2.approx.f32 %0, %1;" : "=f"(y) : "f"(x)); return y;
}
__device__ __forceinline__ uint32_t pack_bf2(float lo, float hi){
    uint32_t u; asm("cvt.rn.bf16x2.f32 %0, %1, %2;" : "=r"(u) : "f"(hi), "f"(lo)); return u;
}
__device__ __forceinline__ void ldmx4(uint32_t& r0,uint32_t& r1,uint32_t& r2,uint32_t& r3, const void* p){
    uint32_t a = (uint32_t)__cvta_generic_to_shared(p);
    asm volatile("ldmatrix.sync.aligned.m8n8.x4.shared.b16 {%0,%1,%2,%3}, [%4];"
        : "=r"(r0),"=r"(r1),"=r"(r2),"=r"(r3) : "r"(a));
}
__device__ __forceinline__ void ldmx4t(uint32_t& r0,uint32_t& r1,uint32_t& r2,uint32_t& r3, const void* p){
    uint32_t a = (uint32_t)__cvta_generic_to_shared(p);
    asm volatile("ldmatrix.sync.aligned.m8n8.x4.trans.shared.b16 {%0,%1,%2,%3}, [%4];"
        : "=r"(r0),"=r"(r1),"=r"(r2),"=r"(r3) : "r"(a));
}
__device__ __forceinline__ void mma16816(float* c, const uint32_t* a,
                                         uint32_t b0,uint32_t b1){
    asm volatile("mma.sync.aligned.m16n8k16.row.col.f32.bf16.bf16.f32 "
        "{%0,%1,%2,%3}, {%4,%5,%6,%7}, {%8,%9}, {%0,%1,%2,%3};"
        : "+f"(c[0]),"+f"(c[1]),"+f"(c[2]),"+f"(c[3])
        : "r"(a[0]),"r"(a[1]),"r"(a[2]),"r"(a[3]),"r"(b0),"r"(b1));
}
__device__ __forceinline__ void cp_async16(void* dst, const void* src){
    uint32_t a = (uint32_t)__cvta_generic_to_shared(dst);
    asm volatile("cp.async.cg.shared.global [%0], [%1], 16;" :: "r"(a), "l"(src) : "memory");
}
#define CP_COMMIT  asm volatile("cp.async.commit_group;" ::: "memory")
template<int N> __device__ __forceinline__ void cp_wait(){
    asm volatile("cp.async.wait_group %0;" :: "n"(N) : "memory");
}

// ---------------- prep: bf16 convert + norms/rowsums, zero accumulators ----------------
__global__ void prep_kernel(const float* __restrict__ x, const float* __restrict__ wq,
                            const float* __restrict__ wo){
    int r = blockIdx.x;
    const float* src; __nv_bfloat16* dstb; float* dsq; float* drs = nullptr;
    if (r < M_TOT)              { src = x  + (size_t)r*DD; dstb = g_xb  + (size_t)r*DD; dsq = g_xsq + r; }
    else if (r < M_TOT + NQKV)  { int rr = r - M_TOT; src = wq + (size_t)rr*DD; dstb = g_wqb + (size_t)rr*DD; dsq = g_wqsq + rr; }
    else { int rr = r - M_TOT - NQKV; src = wo + (size_t)rr*DD; dstb = g_wob + (size_t)rr*DD; dsq = g_wosq + rr; drs = g_wrs + rr; }

    if (r < 512) g_ksq[r*128 + threadIdx.x] = 0.f;   // zero 32*2048 k-norm accumulators

    float4 v = ((const float4*)src)[threadIdx.x];    // 128 thr * 4 = 512
    __nv_bfloat16 b0=__float2bfloat16(v.x), b1=__float2bfloat16(v.y);
    __nv_bfloat16 b2=__float2bfloat16(v.z), b3=__float2bfloat16(v.w);
    __nv_bfloat162 h0; h0.x=b0; h0.y=b1;
    __nv_bfloat162 h1; h1.x=b2; h1.y=b3;
    __nv_bfloat162* d2 = (__nv_bfloat162*)(dstb + threadIdx.x*4);
    d2[0]=h0; d2[1]=h1;
    float f0=__bfloat162float(b0), f1=__bfloat162float(b1);
    float f2=__bfloat162float(b2), f3=__bfloat162float(b3);
    float ss = f0*f0 + f1*f1 + f2*f2 + f3*f3;
    float rs = f0 + f1 + f2 + f3;
    #pragma unroll
    for (int o=16;o>0;o>>=1){ ss += __shfl_xor_sync(~0u, ss, o); rs += __shfl_xor_sync(~0u, rs, o); }
    __shared__ float wsum[4], wsum2[4];
    if ((threadIdx.x&31)==0){ wsum[threadIdx.x>>5]=ss; wsum2[threadIdx.x>>5]=rs; }
    __syncthreads();
    if (threadIdx.x==0){
        *dsq = wsum[0]+wsum[1]+wsum[2]+wsum[3];
        if (drs) *drs = wsum2[0]+wsum2[1]+wsum2[2]+wsum2[3];
        if (r < M_TOT) g_osq[r] = 0.f;
    }
}

// ===================== GEMMs: CTA 128x64, warp 32x32, K-chunk 32, 3-stage =====================
// stage layout: A [128][40] bf16 = 10240 B, B [64][40] bf16 = 5120 B  -> 15360 B/stage
#define GST 15360
#define GSM_BYTES (3*GST)

// mainloop body shared by both GEMM kernels via macro-free duplication (simple + safe)

// ---------------- QKV GEMM ----------------
__global__ __launch_bounds__(256,3) void qkv_gemm_tc(){
    extern __shared__ char smc[];
    int tid=threadIdx.x, lane=tid&31, wid=tid>>5;
    int wr=wid>>1, wc=wid&1;
    int m0=blockIdx.y*128, n0=blockIdx.x*64;
    float acc[2][4][4];
    #pragma unroll
    for(int i=0;i<2;i++) for(int j=0;j<4;j++) for(int k=0;k<4;k++) acc[i][j][k]=0.f;

    auto load_stage = [&](int kt, int st){
        __nv_bfloat16* As = (__nv_bfloat16*)(smc + st*GST);
        __nv_bfloat16* Bs = (__nv_bfloat16*)(smc + st*GST + 10240);
        #pragma unroll
        for (int u=0;u<2;u++){
            int idx=tid+256*u; int row=idx>>2; int q=idx&3;
            cp_async16(&As[row*40+q*8], &g_xb[(size_t)(m0+row)*DD + kt + q*8]);
        }
        { int row=tid>>2; int q=tid&3;
          cp_async16(&Bs[row*40+q*8], &g_wqb[(size_t)(n0+row)*DD + kt + q*8]); }
    };
    load_stage(0, 0);  CP_COMMIT;
    load_stage(32, 1); CP_COMMIT;

    for (int it=0; it<16; it++){
        int st = it%3;
        if (it<15) cp_wait<1>(); else cp_wait<0>();
        __syncthreads();
        if (it+2 < 16){ load_stage((it+2)*32, (it+2)%3); CP_COMMIT; }
        __nv_bfloat16* As = (__nv_bfloat16*)(smc + st*GST);
        __nv_bfloat16* Bs = (__nv_bfloat16*)(smc + st*GST + 10240);
        #pragma unroll
        for (int kc=0;kc<2;kc++){
            uint32_t a[2][4];
            #pragma unroll
            for (int mt=0;mt<2;mt++)
                ldmx4(a[mt][0],a[mt][1],a[mt][2],a[mt][3],
                      &As[(wr*32+mt*16+(lane&15))*40 + kc*16 + (lane>>4)*8]);
            #pragma unroll
            for (int p=0;p<2;p++){
                uint32_t b0,b1,b2,b3;
                ldmx4(b0,b1,b2,b3,
                      &Bs[(wc*32+p*16+(lane>>4)*8+(lane&7))*40 + kc*16 + ((lane>>3)&1)*8]);
                #pragma unroll
                for (int mt=0;mt<2;mt++){
                    mma16816(acc[mt][2*p],   a[mt], b0,b1);
                    mma16816(acc[mt][2*p+1], a[mt], b2,b3);
                }
            }
        }
    }
    int colbase = n0 + wc*32;
    int part = colbase>>9, rem = colbase&511, h = rem>>6, dbase = rem&63;
    #pragma unroll
    for (int mt=0;mt<2;mt++){
        #pragma unroll
        for (int hh=0;hh<2;hh++){
            int m = m0 + wr*32 + mt*16 + (lane>>2) + 8*hh;
            int b = m>>11, n = m&2047;
            float xs = g_xsq[m];
            __nv_bfloat16* orow = g_qkvb + ((size_t)(part*32 + b*8 + h)*NN + n)*DH;
            float ss = 0.f;
            #pragma unroll
            for (int nt=0;nt<4;nt++){
                int col = colbase + nt*8 + 2*(lane&3);
                float d0 = acc[mt][nt][2*hh], d1 = acc[mt][nt][2*hh+1];
                float v0 = sqrtf(fmaxf(xs + g_wqsq[col]   - 2.f*d0, 0.f)) - 32.f;
                float v1 = sqrtf(fmaxf(xs + g_wqsq[col+1] - 2.f*d1, 0.f)) - 32.f;
                __nv_bfloat162 h2; h2.x=__float2bfloat16(v0); h2.y=__float2bfloat16(v1);
                *(__nv_bfloat162*)&orow[dbase + nt*8 + 2*(lane&3)] = h2;
                ss += v0*v0 + v1*v1;
            }
            if (part == 1){   // only k-norms needed (q-norm cancels in softmax)
                ss += __shfl_xor_sync(~0u, ss, 1);
                ss += __shfl_xor_sync(~0u, ss, 2);
                if ((lane&3)==0) atomicAdd(&g_ksq[(b*8 + h)*NN + n], ss);
            }
        }
    }
}

// ---------------- output GEMM ----------------
__global__ __launch_bounds__(256,3) void out_gemm_tc(float* __restrict__ out){
    extern __shared__ char smc[];
    int tid=threadIdx.x, lane=tid&31, wid=tid>>5;
    int wr=wid>>1, wc=wid&1;
    int m0=blockIdx.y*128, n0=blockIdx.x*64;
    float acc[2][4][4];
    #pragma unroll
    for(int i=0;i<2;i++) for(int j=0;j<4;j++) for(int k=0;k<4;k++) acc[i][j][k]=0.f;

    auto load_stage = [&](int kt, int st){
        __nv_bfloat16* As = (__nv_bfloat16*)(smc + st*GST);
        __nv_bfloat16* Bs = (__nv_bfloat16*)(smc + st*GST + 10240);
        #pragma unroll
        for (int u=0;u<2;u++){
            int idx=tid+256*u; int row=idx>>2; int q=idx&3;
            cp_async16(&As[row*40+q*8], &g_ob[(size_t)(m0+row)*DD + kt + q*8]);
        }
        { int row=tid>>2; int q=tid&3;
          cp_async16(&Bs[row*40+q*8], &g_wob[(size_t)(n0+row)*DD + kt + q*8]); }
    };
    load_stage(0, 0);  CP_COMMIT;
    load_stage(32, 1); CP_COMMIT;

    for (int it=0; it<16; it++){
        int st = it%3;
        if (it<15) cp_wait<1>(); else cp_wait<0>();
        __syncthreads();
        if (it+2 < 16){ load_stage((it+2)*32, (it+2)%3); CP_COMMIT; }
        __nv_bfloat16* As = (__nv_bfloat16*)(smc + st*GST);
        __nv_bfloat16* Bs = (__nv_bfloat16*)(smc + st*GST + 10240);
        #pragma unroll
        for (int kc=0;kc<2;kc++){
            uint32_t a[2][4];
            #pragma unroll
            for (int mt=0;mt<2;mt++)
                ldmx4(a[mt][0],a[mt][1],a[mt][2],a[mt][3],
                      &As[(wr*32+mt*16+(lane&15))*40 + kc*16 + (lane>>4)*8]);
            #pragma unroll
            for (int p=0;p<2;p++){
                uint32_t b0,b1,b2,b3;
                ldmx4(b0,b1,b2,b3,
                      &Bs[(wc*32+p*16+(lane>>4)*8+(lane&7))*40 + kc*16 + ((lane>>3)&1)*8]);
                #pragma unroll
                for (int mt=0;mt<2;mt++){
                    mma16816(acc[mt][2*p],   a[mt], b0,b1);
                    mma16816(acc[mt][2*p+1], a[mt], b2,b3);
                }
            }
        }
    }
    #pragma unroll
    for (int mt=0;mt<2;mt++){
        #pragma unroll
        for (int hh=0;hh<2;hh++){
            int m = m0 + wr*32 + mt*16 + (lane>>2) + 8*hh;
            float os = g_osq[m];
            #pragma unroll
            for (int nt=0;nt<4;nt++){
                int col = n0 + wc*32 + nt*8 + 2*(lane&3);
                float dot0 = acc[mt][nt][2*hh]   + 32.f*g_wrs[col];
                float dot1 = acc[mt][nt][2*hh+1] + 32.f*g_wrs[col+1];
                out[(size_t)m*DD + col]   = sqrtf(fmaxf(os + g_wosq[col]   - 2.f*dot0, 0.f));
                out[(size_t)m*DD + col+1] = sqrtf(fmaxf(os + g_wosq[col+1] - 2.f*dot1, 0.f));
            }
        }
    }
}

// ---------------- flash attention: 3-stage ring, ONE sync per j-tile, no q-norm ----------------
// smem: Qs [128][72] = 18432 | stage s at 18432+s*18688: K(9216) V(9216) ksq(256)
#define FSTAGE 18688
#define FSM_BYTES (18432 + 3*FSTAGE)
__global__ __launch_bounds__(256,2) void flash_tc(){
    extern __shared__ char smem[];
    __nv_bfloat16* Qs = (__nv_bfloat16*)smem;

    int tid=threadIdx.x, lane=tid&31, w=tid>>5;
    int bh = blockIdx.y; int i0 = blockIdx.x*128;
    const __nv_bfloat16* qg = g_qkvb + ((size_t)(0*32+bh)*NN + i0)*DH;
    const __nv_bfloat16* kg = g_qkvb + (size_t)(1*32+bh)*NN*DH;
    const __nv_bfloat16* vg = g_qkvb + (size_t)(2*32+bh)*NN*DH;
    const float* ksqg = g_ksq + (size_t)bh*NN;

    auto load_stage = [&](int j0, int st){
        char* base = smem + 18432 + st*FSTAGE;
        __nv_bfloat16* Ks = (__nv_bfloat16*)base;
        __nv_bfloat16* Vs = (__nv_bfloat16*)(base + 9216);
        float* kq = (float*)(base + 18432);
        #pragma unroll
        for (int u=0;u<2;u++){
            int idx=tid+256*u; int row=idx>>3; int q=idx&7;
            cp_async16(&Ks[row*72+q*8], &kg[(size_t)(j0+row)*DH+q*8]);
            cp_async16(&Vs[row*72+q*8], &vg[(size_t)(j0+row)*DH+q*8]);
        }
        if (tid<16) cp_async16(&kq[tid*4], &ksqg[j0+tid*4]);
    };

    // Q (own group), then stage 0, stage 1
    #pragma unroll
    for (int u=0;u<4;u++){
        int idx=tid+256*u; int row=idx>>3; int q=idx&7;
        cp_async16(&Qs[row*72+q*8], &qg[(size_t)row*DH + q*8]);
    }
    CP_COMMIT;
    load_stage(0, 0);  CP_COMMIT;
    load_stage(64, 1); CP_COMMIT;

    cp_wait<2>();             // Q complete
    __syncthreads();

    // hoist Q fragments: warp w owns rows [16w, 16w+16)
    uint32_t qf[4][4];
    #pragma unroll
    for (int kc=0;kc<4;kc++)
        ldmx4(qf[kc][0],qf[kc][1],qf[kc][2],qf[kc][3],
              &Qs[(w*16+(lane&15))*72 + kc*16 + (lane>>4)*8]);

    float lr[2] = {0.f, 0.f};
    float accO[8][4];
    #pragma unroll
    for (int j=0;j<8;j++) for (int k=0;k<4;k++) accO[j][k]=0.f;

    const float C1 = 0.25f*LOG2E, C2 = 0.125f*LOG2E;

    for (int t=0; t<32; t++){
        int st = t%3;
        if (t<31) cp_wait<1>(); else cp_wait<0>();
        __syncthreads();
        if (t+2 < 32){ load_stage((t+2)*64, (t+2)%3); CP_COMMIT; }
        char* base = smem + 18432 + st*FSTAGE;
        __nv_bfloat16* Ks = (__nv_bfloat16*)base;
        __nv_bfloat16* Vs = (__nv_bfloat16*)(base + 9216);
        const float* ksq = (const float*)(base + 18432);

        // S = Q.K^T : 16 rows x 64 j per warp
        float s[8][4];
        #pragma unroll
        for(int j=0;j<8;j++) for(int k=0;k<4;k++) s[j][k]=0.f;
        #pragma unroll
        for (int kc=0;kc<4;kc++){
            #pragma unroll
            for (int p=0;p<4;p++){
                uint32_t b0,b1,b2,b3;
                ldmx4(b0,b1,b2,b3,
                      &Ks[(p*16+(lane>>4)*8+(lane&7))*72 + kc*16 + ((lane>>3)&1)*8]);
                mma16816(s[2*p],   qf[kc], b0,b1);
                mma16816(s[2*p+1], qf[kc], b2,b3);
            }
        }

        // p = exp2(C1*s - C2*|k|^2)  (q-norm term cancels in the softmax ratio)
        #pragma unroll
        for (int hh=0;hh<2;hh++){
            float rs=0.f;
            #pragma unroll
            for (int nt=0;nt<8;nt++){
                int col = nt*8 + 2*(lane&3);
                float p0 = fast_exp2(C1*s[nt][2*hh]   - C2*ksq[col]);
                float p1 = fast_exp2(C1*s[nt][2*hh+1] - C2*ksq[col+1]);
                s[nt][2*hh]=p0; s[nt][2*hh+1]=p1; rs += p0+p1;
            }
            rs += __shfl_xor_sync(~0u,rs,1);
            rs += __shfl_xor_sync(~0u,rs,2);
            lr[hh] += rs;
        }

        // O += P.V
        #pragma unroll
        for (int kc=0;kc<4;kc++){
            uint32_t pa[4];
            pa[0]=pack_bf2(s[2*kc][0],   s[2*kc][1]);
            pa[1]=pack_bf2(s[2*kc][2],   s[2*kc][3]);
            pa[2]=pack_bf2(s[2*kc+1][0], s[2*kc+1][1]);
            pa[3]=pack_bf2(s[2*kc+1][2], s[2*kc+1][3]);
            #pragma unroll
            for (int dp=0;dp<4;dp++){
                uint32_t b0,b1,b2,b3;
                ldmx4t(b0,b1,b2,b3,
                       &Vs[(kc*16+((lane>>3)&1)*8+(lane&7))*72 + dp*16 + (lane>>4)*8]);
                mma16816(accO[2*dp],   pa, b0,b1);
                mma16816(accO[2*dp+1], pa, b2,b3);
            }
        }
    }

    // epilogue: warp-private rows
    int b = bh>>3, h = bh&7;
    #pragma unroll
    for (int hh=0;hh<2;hh++){
        int row = w*16 + (lane>>2) + 8*hh;
        float inv = 1.f/lr[hh];
        __nv_bfloat16* orow = g_ob + (size_t)(b*NN + i0 + row)*DD + h*DH;
        float ss = 0.f;
        #pragma unroll
        for (int nt=0;nt<8;nt++){
            int col = nt*8 + 2*(lane&3);
            float o0 = accO[nt][2*hh]*inv;
            float o1 = accO[nt][2*hh+1]*inv;
            __nv_bfloat162 h2; h2.x=__float2bfloat16(o0); h2.y=__float2bfloat16(o1);
            *(__nv_bfloat162*)&orow[col] = h2;
            float a0=o0+32.f, a1=o1+32.f;
            ss += a0*a0 + a1*a1;
        }
        ss += __shfl_xor_sync(~0u, ss, 1);
        ss += __shfl_xor_sync(~0u, ss, 2);
        if ((lane&3)==0) atomicAdd(&g_osq[b*NN + i0 + row], ss);
    }
}

// ---------------- launch ----------------
extern "C" void kernel_launch(void* const* d_in, const int* in_sizes, int n_in,
                              void* d_out, int out_size) {
    const float* x    = (const float*)d_in[0];
    const float* wqkv = (const float*)d_in[1];
    const float* wout = (const float*)d_in[2];
    float* out = (float*)d_out;

    cudaFuncSetAttribute(qkv_gemm_tc, cudaFuncAttributeMaxDynamicSharedMemorySize, GSM_BYTES);
    cudaFuncSetAttribute(out_gemm_tc, cudaFuncAttributeMaxDynamicSharedMemorySize, GSM_BYTES);
    cudaFuncSetAttribute(flash_tc,    cudaFuncAttributeMaxDynamicSharedMemorySize, FSM_BYTES);

    prep_kernel<<<M_TOT + NQKV + DD, 128>>>(x, wqkv, wout);
    qkv_gemm_tc<<<dim3(NQKV/64, M_TOT/128), 256, GSM_BYTES>>>();
    flash_tc<<<dim3(NN/128, 32), 256, FSM_BYTES>>>();
    out_gemm_tc<<<dim3(DD/64, M_TOT/128), 256, GSM_BYTES>>>(out);
}

// round 11
// speedup vs baseline: 7.3108x; 1.0465x over previous
#include <cuda_runtime.h>
#include <cuda_fp16.h>
#include <math.h>
#include <stdint.h>

#define BB 4
#define HH 8
#define NN 2048
#define DD 512
#define DH 64
#define M_TOT (BB*NN)          // 8192
#define NQKV (3*DD)            // 1536
#define LOG2E 1.4426950408889634f

// ---------------- device scratch ----------------
__device__ __align__(16) __half g_xh [(size_t)M_TOT*DD];
__device__ __align__(16) __half g_wqh[(size_t)NQKV*DD];
__device__ __align__(16) __half g_woh[(size_t)DD*DD];
__device__ __align__(16) __half g_qkvh[(size_t)3*32*NN*DH];  // centered q,k,v
__device__ __align__(16) __half g_oh[(size_t)M_TOT*DD];      // centered attn out
__device__ float g_xsq[M_TOT];
__device__ float g_wqsq[NQKV];
__device__ float g_wosq[DD];
__device__ float g_wrs[DD];                          // row-sums of w_out
__device__ float g_osq[M_TOT];
__device__ __align__(16) float g_qksq[2*32*NN];      // centered |q|^2, |k|^2 per (bh,n)

// ---------------- helpers ----------------
__device__ __forceinline__ void ldmx4(uint32_t& r0,uint32_t& r1,uint32_t& r2,uint32_t& r3, const void* p){
    uint32_t a = (uint32_t)__cvta_generic_to_shared(p);
    asm volatile("ldmatrix.sync.aligned.m8n8.x4.shared.b16 {%0,%1,%2,%3}, [%4];"
        : "=r"(r0),"=r"(r1),"=r"(r2),"=r"(r3) : "r"(a));
}
__device__ __forceinline__ void ldmx4t(uint32_t& r0,uint32_t& r1,uint32_t& r2,uint32_t& r3, const void* p){
    uint32_t a = (uint32_t)__cvta_generic_to_shared(p);
    asm volatile("ldmatrix.sync.aligned.m8n8.x4.trans.shared.b16 {%0,%1,%2,%3}, [%4];"
        : "=r"(r0),"=r"(r1),"=r"(r2),"=r"(r3) : "r"(a));
}
// fp16-accumulate MMA: D,C are 2 x .f16x2 regs
__device__ __forceinline__ void mmaf16(uint32_t* c, const uint32_t* a, uint32_t b0, uint32_t b1){
    asm volatile("mma.sync.aligned.m16n8k16.row.col.f16.f16.f16.f16 "
        "{%0,%1}, {%2,%3,%4,%5}, {%6,%7}, {%0,%1};"
        : "+r"(c[0]),"+r"(c[1])
        : "r"(a[0]),"r"(a[1]),"r"(a[2]),"r"(a[3]),"r"(b0),"r"(b1));
}
__device__ __forceinline__ void cp_async16(void* dst, const void* src){
    uint32_t a = (uint32_t)__cvta_generic_to_shared(dst);
    asm volatile("cp.async.cg.shared.global [%0], [%1], 16;" :: "r"(a), "l"(src) : "memory");
}
#define CP_COMMIT  asm volatile("cp.async.commit_group;" ::: "memory")
template<int N> __device__ __forceinline__ void cp_wait(){
    asm volatile("cp.async.wait_group %0;" :: "n"(N) : "memory");
}
__device__ __forceinline__ uint32_t h2exp2(uint32_t t){
    uint32_t p; asm("ex2.approx.f16x2 %0, %1;" : "=r"(p) : "r"(t)); return p;
}

// ---------------- prep: fp16 convert + norms/rowsums, zero accumulators ----------------
__global__ void prep_kernel(const float* __restrict__ x, const float* __restrict__ wq,
                            const float* __restrict__ wo){
    int r = blockIdx.x;
    const float* src; __half* dstb; float* dsq; float* drs = nullptr;
    if (r < M_TOT)              { src = x  + (size_t)r*DD; dstb = g_xh  + (size_t)r*DD; dsq = g_xsq + r; }
    else if (r < M_TOT + NQKV)  { int rr = r - M_TOT; src = wq + (size_t)rr*DD; dstb = g_wqh + (size_t)rr*DD; dsq = g_wqsq + rr; }
    else { int rr = r - M_TOT - NQKV; src = wo + (size_t)rr*DD; dstb = g_woh + (size_t)rr*DD; dsq = g_wosq + rr; drs = g_wrs + rr; }

    if (r < 1024) g_qksq[r*128 + threadIdx.x] = 0.f;   // zero 2*32*2048 norm accumulators

    float4 v = ((const float4*)src)[threadIdx.x];
    __half2 h0 = __floats2half2_rn(v.x, v.y);
    __half2 h1 = __floats2half2_rn(v.z, v.w);
    __half2* d2 = (__half2*)(dstb + threadIdx.x*4);
    d2[0]=h0; d2[1]=h1;
    float2 f0 = __half22float2(h0), f1 = __half22float2(h1);
    float ss = f0.x*f0.x + f0.y*f0.y + f1.x*f1.x + f1.y*f1.y;
    float rs = f0.x + f0.y + f1.x + f1.y;
    #pragma unroll
    for (int o=16;o>0;o>>=1){ ss += __shfl_xor_sync(~0u, ss, o); rs += __shfl_xor_sync(~0u, rs, o); }
    __shared__ float wsum[4], wsum2[4];
    if ((threadIdx.x&31)==0){ wsum[threadIdx.x>>5]=ss; wsum2[threadIdx.x>>5]=rs; }
    __syncthreads();
    if (threadIdx.x==0){
        *dsq = wsum[0]+wsum[1]+wsum[2]+wsum[3];
        if (drs) *drs = wsum2[0]+wsum2[1]+wsum2[2]+wsum2[3];
        if (r < M_TOT) g_osq[r] = 0.f;
    }
}

// ===================== GEMMs: CTA 128x128, warp 32x64, K=64, 3-stage, fp16 acc =====================
#define GSM_BYTES (3*36864)

// ---------------- QKV GEMM ----------------
__global__ __launch_bounds__(256) void qkv_gemm_tc(){
    extern __shared__ char smc[];
    int tid=threadIdx.x, lane=tid&31, wid=tid>>5;
    int wr=wid>>1, wc=wid&1;
    int m0=blockIdx.y*128, n0=blockIdx.x*128;
    uint32_t acc[2][8][2];
    #pragma unroll
    for(int i=0;i<2;i++) for(int j=0;j<8;j++){ acc[i][j][0]=0u; acc[i][j][1]=0u; }

    auto load_stage = [&](int kt, int st){
        __half* As = (__half*)(smc + st*36864);
        __half* Bs = (__half*)(smc + st*36864 + 18432);
        #pragma unroll
        for (int u=0;u<4;u++){
            int idx=tid+256*u; int row=idx>>3; int q=idx&7;
            cp_async16(&As[row*72+q*8], &g_xh [(size_t)(m0+row)*DD + kt + q*8]);
            cp_async16(&Bs[row*72+q*8], &g_wqh[(size_t)(n0+row)*DD + kt + q*8]);
        }
    };
    load_stage(0, 0);  CP_COMMIT;
    load_stage(64, 1); CP_COMMIT;

    for (int it=0; it<8; it++){
        int st = it%3;
        if (it<7) cp_wait<1>(); else cp_wait<0>();
        __syncthreads();
        if (it+2 < 8){ load_stage((it+2)*64, (it+2)%3); CP_COMMIT; }
        __half* As = (__half*)(smc + st*36864);
        __half* Bs = (__half*)(smc + st*36864 + 18432);
        #pragma unroll
        for (int kc=0;kc<4;kc++){
            uint32_t a[2][4];
            #pragma unroll
            for (int mt=0;mt<2;mt++)
                ldmx4(a[mt][0],a[mt][1],a[mt][2],a[mt][3],
                      &As[(wr*32+mt*16+(lane&15))*72 + kc*16 + (lane>>4)*8]);
            #pragma unroll
            for (int p=0;p<4;p++){
                uint32_t b0,b1,b2,b3;
                ldmx4(b0,b1,b2,b3,
                      &Bs[(wc*64+p*16+(lane>>4)*8+(lane&7))*72 + kc*16 + ((lane>>3)&1)*8]);
                #pragma unroll
                for (int mt=0;mt<2;mt++){
                    mmaf16(acc[mt][2*p],   a[mt], b0,b1);
                    mmaf16(acc[mt][2*p+1], a[mt], b2,b3);
                }
            }
        }
    }
    int colbase = n0 + wc*64;
    int part = colbase>>9, rem = colbase&511, h = rem>>6, dbase = rem&63;
    #pragma unroll
    for (int mt=0;mt<2;mt++){
        #pragma unroll
        for (int hh=0;hh<2;hh++){
            int m = m0 + wr*32 + mt*16 + (lane>>2) + 8*hh;
            int b = m>>11, n = m&2047;
            float xs = g_xsq[m];
            __half* orow = g_qkvh + ((size_t)(part*32 + b*8 + h)*NN + n)*DH;
            float ss = 0.f;
            #pragma unroll
            for (int nt=0;nt<8;nt++){
                int col = colbase + nt*8 + 2*(lane&3);
                float2 dd = __half22float2(*(__half2*)&acc[mt][nt][hh]);
                float v0 = sqrtf(fmaxf(xs + g_wqsq[col]   - 2.f*dd.x, 0.f)) - 32.f;
                float v1 = sqrtf(fmaxf(xs + g_wqsq[col+1] - 2.f*dd.y, 0.f)) - 32.f;
                __half2 h2 = __floats2half2_rn(v0, v1);
                *(__half2*)&orow[dbase + nt*8 + 2*(lane&3)] = h2;
                float2 rr = __half22float2(h2);           // norms from ROUNDED values
                ss += rr.x*rr.x + rr.y*rr.y;
            }
            if (part < 2){                                // q- AND k-norms
                ss += __shfl_xor_sync(~0u, ss, 1);
                ss += __shfl_xor_sync(~0u, ss, 2);
                if ((lane&3)==0) atomicAdd(&g_qksq[(part*32 + b*8 + h)*NN + n], ss);
            }
        }
    }
}

// ---------------- output GEMM ----------------
__global__ __launch_bounds__(256) void out_gemm_tc(float* __restrict__ out){
    extern __shared__ char smc[];
    int tid=threadIdx.x, lane=tid&31, wid=tid>>5;
    int wr=wid>>1, wc=wid&1;
    int m0=blockIdx.y*128, n0=blockIdx.x*128;
    uint32_t acc[2][8][2];
    #pragma unroll
    for(int i=0;i<2;i++) for(int j=0;j<8;j++){ acc[i][j][0]=0u; acc[i][j][1]=0u; }

    auto load_stage = [&](int kt, int st){
        __half* As = (__half*)(smc + st*36864);
        __half* Bs = (__half*)(smc + st*36864 + 18432);
        #pragma unroll
        for (int u=0;u<4;u++){
            int idx=tid+256*u; int row=idx>>3; int q=idx&7;
            cp_async16(&As[row*72+q*8], &g_oh [(size_t)(m0+row)*DD + kt + q*8]);
            cp_async16(&Bs[row*72+q*8], &g_woh[(size_t)(n0+row)*DD + kt + q*8]);
        }
    };
    load_stage(0, 0);  CP_COMMIT;
    load_stage(64, 1); CP_COMMIT;

    for (int it=0; it<8; it++){
        int st = it%3;
        if (it<7) cp_wait<1>(); else cp_wait<0>();
        __syncthreads();
        if (it+2 < 8){ load_stage((it+2)*64, (it+2)%3); CP_COMMIT; }
        __half* As = (__half*)(smc + st*36864);
        __half* Bs = (__half*)(smc + st*36864 + 18432);
        #pragma unroll
        for (int kc=0;kc<4;kc++){
            uint32_t a[2][4];
            #pragma unroll
            for (int mt=0;mt<2;mt++)
                ldmx4(a[mt][0],a[mt][1],a[mt][2],a[mt][3],
                      &As[(wr*32+mt*16+(lane&15))*72 + kc*16 + (lane>>4)*8]);
            #pragma unroll
            for (int p=0;p<4;p++){
                uint32_t b0,b1,b2,b3;
                ldmx4(b0,b1,b2,b3,
                      &Bs[(wc*64+p*16+(lane>>4)*8+(lane&7))*72 + kc*16 + ((lane>>3)&1)*8]);
                #pragma unroll
                for (int mt=0;mt<2;mt++){
                    mmaf16(acc[mt][2*p],   a[mt], b0,b1);
                    mmaf16(acc[mt][2*p+1], a[mt], b2,b3);
                }
            }
        }
    }
    #pragma unroll
    for (int mt=0;mt<2;mt++){
        #pragma unroll
        for (int hh=0;hh<2;hh++){
            int m = m0 + wr*32 + mt*16 + (lane>>2) + 8*hh;
            float os = g_osq[m];
            #pragma unroll
            for (int nt=0;nt<8;nt++){
                int col = n0 + wc*64 + nt*8 + 2*(lane&3);
                float2 dd = __half22float2(*(__half2*)&acc[mt][nt][hh]);
                float dot0 = dd.x + 32.f*g_wrs[col];
                float dot1 = dd.y + 32.f*g_wrs[col+1];
                out[(size_t)m*DD + col]   = sqrtf(fmaxf(os + g_wosq[col]   - 2.f*dot0, 0.f));
                out[(size_t)m*DD + col+1] = sqrtf(fmaxf(os + g_wosq[col+1] - 2.f*dot1, 0.f));
            }
        }
    }
}

// ---------------- flash attention: fp16 end-to-end, bounded exponent, 3-stage ring ----------------
// smem: Qs [128][72] = 18432 | stage s at 18432+s*18688: K(9216) V(9216) ksq(256)
#define FSTAGE 18688
#define FSM_BYTES (18432 + 3*FSTAGE)
__global__ __launch_bounds__(256,2) void flash_tc(){
    extern __shared__ char smem[];
    __half* Qs = (__half*)smem;

    int tid=threadIdx.x, lane=tid&31, w=tid>>5;
    int bh = blockIdx.y; int i0 = blockIdx.x*128;
    const __half* qg = g_qkvh + ((size_t)(0*32+bh)*NN + i0)*DH;
    const __half* kg = g_qkvh + (size_t)(1*32+bh)*NN*DH;
    const __half* vg = g_qkvh + (size_t)(2*32+bh)*NN*DH;
    const float* qsqg = g_qksq + (size_t)(0*32+bh)*NN + i0;
    const float* ksqg = g_qksq + (size_t)(1*32+bh)*NN;

    auto load_stage = [&](int j0, int st){
        char* base = smem + 18432 + st*FSTAGE;
        __half* Ks = (__half*)base;
        __half* Vs = (__half*)(base + 9216);
        float* kq = (float*)(base + 18432);
        #pragma unroll
        for (int u=0;u<2;u++){
            int idx=tid+256*u; int row=idx>>3; int q=idx&7;
            cp_async16(&Ks[row*72+q*8], &kg[(size_t)(j0+row)*DH+q*8]);
            cp_async16(&Vs[row*72+q*8], &vg[(size_t)(j0+row)*DH+q*8]);
        }
        if (tid<16) cp_async16(&kq[tid*4], &ksqg[j0+tid*4]);
    };

    #pragma unroll
    for (int u=0;u<4;u++){
        int idx=tid+256*u; int row=idx>>3; int q=idx&7;
        cp_async16(&Qs[row*72+q*8], &qg[(size_t)row*DH + q*8]);
    }
    CP_COMMIT;
    load_stage(0, 0);  CP_COMMIT;
    load_stage(64, 1); CP_COMMIT;

    cp_wait<2>();
    __syncthreads();

    uint32_t qf[4][4];
    #pragma unroll
    for (int kc=0;kc<4;kc++)
        ldmx4(qf[kc][0],qf[kc][1],qf[kc][2],qf[kc][3],
              &Qs[(w*16+(lane&15))*72 + kc*16 + (lane>>4)*8]);

    const float C2 = 0.125f*LOG2E;
    const float BIAS = 12.0f;                 // logit = BIAS - C2*d^2 <= BIAS -> p <= 4096 (fp16-safe)
    const __half2 C1h = __float2half2_rn(0.25f*LOG2E);
    // per-row constants (q-norm bounds the exponent; cancels exactly in accO/l)
    float rowc0 = BIAS - C2*qsqg[w*16 + (lane>>2)];
    float rowc1 = BIAS - C2*qsqg[w*16 + (lane>>2) + 8];

    float lr[2] = {0.f, 0.f};
    uint32_t accO[8][2];
    #pragma unroll
    for (int j=0;j<8;j++){ accO[j][0]=0u; accO[j][1]=0u; }

    for (int t=0; t<32; t++){
        int st = t%3;
        if (t<31) cp_wait<1>(); else cp_wait<0>();
        __syncthreads();
        if (t+2 < 32){ load_stage((t+2)*64, (t+2)%3); CP_COMMIT; }
        char* base = smem + 18432 + st*FSTAGE;
        __half* Ks = (__half*)base;
        __half* Vs = (__half*)(base + 9216);
        const float* ksq = (const float*)(base + 18432);

        // S = Q.K^T (fp16 accum): 16 rows x 64 j per warp
        uint32_t s2[8][2];
        #pragma unroll
        for(int j=0;j<8;j++){ s2[j][0]=0u; s2[j][1]=0u; }
        #pragma unroll
        for (int kc=0;kc<4;kc++){
            #pragma unroll
            for (int p=0;p<4;p++){
                uint32_t b0,b1,b2,b3;
                ldmx4(b0,b1,b2,b3,
                      &Ks[(p*16+(lane>>4)*8+(lane&7))*72 + kc*16 + ((lane>>3)&1)*8]);
                mmaf16(s2[2*p],   qf[kc], b0,b1);
                mmaf16(s2[2*p+1], qf[kc], b2,b3);
            }
        }

        // p = exp2(C1*s + rowc - C2*|k|^2) in half2; result IS the PV A-fragment
        __half2 hs0 = __float2half2_rn(0.f), hs1 = __float2half2_rn(0.f);
        #pragma unroll
        for (int nt=0;nt<8;nt++){
            float2 kf = *(const float2*)&ksq[nt*8 + 2*(lane&3)];
            __half2 c0 = __floats2half2_rn(rowc0 - C2*kf.x, rowc0 - C2*kf.y);
            __half2 c1 = __floats2half2_rn(rowc1 - C2*kf.x, rowc1 - C2*kf.y);
            __half2 t0 = __hfma2(*(__half2*)&s2[nt][0], C1h, c0);
            __half2 t1 = __hfma2(*(__half2*)&s2[nt][1], C1h, c1);
            s2[nt][0] = h2exp2(*(uint32_t*)&t0);
            s2[nt][1] = h2exp2(*(uint32_t*)&t1);
            hs0 = __hadd2(hs0, *(__half2*)&s2[nt][0]);
            hs1 = __hadd2(hs1, *(__half2*)&s2[nt][1]);
        }
        {
            float2 f0 = __half22float2(hs0), f1 = __half22float2(hs1);
            float rs0 = f0.x + f0.y, rs1 = f1.x + f1.y;
            rs0 += __shfl_xor_sync(~0u, rs0, 1); rs0 += __shfl_xor_sync(~0u, rs0, 2);
            rs1 += __shfl_xor_sync(~0u, rs1, 1); rs1 += __shfl_xor_sync(~0u, rs1, 2);
            lr[0] += rs0; lr[1] += rs1;
        }

        // O += P.V (fp16 accum), P fragments = s2 directly
        #pragma unroll
        for (int kc=0;kc<4;kc++){
            uint32_t pa[4] = { s2[2*kc][0], s2[2*kc][1], s2[2*kc+1][0], s2[2*kc+1][1] };
            #pragma unroll
            for (int dp=0;dp<4;dp++){
                uint32_t b0,b1,b2,b3;
                ldmx4t(b0,b1,b2,b3,
                       &Vs[(kc*16+((lane>>3)&1)*8+(lane&7))*72 + dp*16 + (lane>>4)*8]);
                mmaf16(accO[2*dp],   pa, b0,b1);
                mmaf16(accO[2*dp+1], pa, b2,b3);
            }
        }
    }

    // epilogue: warp-private rows
    int b = bh>>3, h = bh&7;
    #pragma unroll
    for (int hh=0;hh<2;hh++){
        int row = w*16 + (lane>>2) + 8*hh;
        float inv = 1.f/lr[hh];
        __half* orow = g_oh + (size_t)(b*NN + i0 + row)*DD + h*DH;
        float ss = 0.f;
        #pragma unroll
        for (int nt=0;nt<8;nt++){
            float2 f = __half22float2(*(__half2*)&accO[nt][hh]);
            float o0 = f.x*inv, o1 = f.y*inv;
            __half2 h2 = __floats2half2_rn(o0, o1);
            *(__half2*)&orow[nt*8 + 2*(lane&3)] = h2;
            float2 rr = __half22float2(h2);
            float a0 = rr.x+32.f, a1 = rr.y+32.f;
            ss += a0*a0 + a1*a1;
        }
        ss += __shfl_xor_sync(~0u, ss, 1);
        ss += __shfl_xor_sync(~0u, ss, 2);
        if ((lane&3)==0) atomicAdd(&g_osq[b*NN + i0 + row], ss);
    }
}

// ---------------- launch ----------------
extern "C" void kernel_launch(void* const* d_in, const int* in_sizes, int n_in,
                              void* d_out, int out_size) {
    const float* x    = (const float*)d_in[0];
    const float* wqkv = (const float*)d_in[1];
    const float* wout = (const float*)d_in[2];
    float* out = (float*)d_out;

    cudaFuncSetAttribute(qkv_gemm_tc, cudaFuncAttributeMaxDynamicSharedMemorySize, GSM_BYTES);
    cudaFuncSetAttribute(out_gemm_tc, cudaFuncAttributeMaxDynamicSharedMemorySize, GSM_BYTES);
    cudaFuncSetAttribute(flash_tc,    cudaFuncAttributeMaxDynamicSharedMemorySize, FSM_BYTES);

    prep_kernel<<<M_TOT + NQKV + DD, 128>>>(x, wqkv, wout);
    qkv_gemm_tc<<<dim3(NQKV/128, M_TOT/128), 256, GSM_BYTES>>>();
    flash_tc<<<dim3(NN/128, 32), 256, FSM_BYTES>>>();
    out_gemm_tc<<<dim3(DD/128, M_TOT/128), 256, GSM_BYTES>>>(out);
}

// round 12
// speedup vs baseline: 7.9034x; 1.0811x over previous
#include <cuda_runtime.h>
#include <cuda_fp16.h>
#include <math.h>
#include <stdint.h>

#define BB 4
#define HH 8
#define NN 2048
#define DD 512
#define DH 64
#define M_TOT (BB*NN)          // 8192
#define NQKV (3*DD)            // 1536
#define LOG2E 1.4426950408889634f

// ---------------- device scratch ----------------
__device__ __align__(16) __half g_xh [(size_t)M_TOT*DD];
__device__ __align__(16) __half g_wqh[(size_t)NQKV*DD];
__device__ __align__(16) __half g_woh[(size_t)DD*DD];
__device__ __align__(16) __half g_qkvh[(size_t)3*32*NN*DH];  // centered q,k,v
__device__ __align__(16) __half g_oh[(size_t)M_TOT*DD];      // centered attn out
__device__ float g_xsq[M_TOT];
__device__ float g_wqsq[NQKV];
__device__ float g_wosq[DD];
__device__ float g_wrs[DD];                          // row-sums of w_out
__device__ float g_osq[M_TOT];
__device__ __align__(16) float g_qksq[2*32*NN];      // centered |q|^2, |k|^2 per (bh,n)

// ---------------- helpers ----------------
__device__ __forceinline__ void ldmx4(uint32_t& r0,uint32_t& r1,uint32_t& r2,uint32_t& r3, const void* p){
    uint32_t a = (uint32_t)__cvta_generic_to_shared(p);
    asm volatile("ldmatrix.sync.aligned.m8n8.x4.shared.b16 {%0,%1,%2,%3}, [%4];"
        : "=r"(r0),"=r"(r1),"=r"(r2),"=r"(r3) : "r"(a));
}
__device__ __forceinline__ void ldmx4t(uint32_t& r0,uint32_t& r1,uint32_t& r2,uint32_t& r3, const void* p){
    uint32_t a = (uint32_t)__cvta_generic_to_shared(p);
    asm volatile("ldmatrix.sync.aligned.m8n8.x4.trans.shared.b16 {%0,%1,%2,%3}, [%4];"
        : "=r"(r0),"=r"(r1),"=r"(r2),"=r"(r3) : "r"(a));
}
// fp16-accumulate MMA: D,C are 2 x .f16x2 regs
__device__ __forceinline__ void mmaf16(uint32_t* c, const uint32_t* a, uint32_t b0, uint32_t b1){
    asm volatile("mma.sync.aligned.m16n8k16.row.col.f16.f16.f16.f16 "
        "{%0,%1}, {%2,%3,%4,%5}, {%6,%7}, {%0,%1};"
        : "+r"(c[0]),"+r"(c[1])
        : "r"(a[0]),"r"(a[1]),"r"(a[2]),"r"(a[3]),"r"(b0),"r"(b1));
}
__device__ __forceinline__ void cp_async16(void* dst, const void* src){
    uint32_t a = (uint32_t)__cvta_generic_to_shared(dst);
    asm volatile("cp.async.cg.shared.global [%0], [%1], 16;" :: "r"(a), "l"(src) : "memory");
}
#define CP_COMMIT  asm volatile("cp.async.commit_group;" ::: "memory")
template<int N> __device__ __forceinline__ void cp_wait(){
    asm volatile("cp.async.wait_group %0;" :: "n"(N) : "memory");
}
__device__ __forceinline__ uint32_t h2exp2(uint32_t t){
    uint32_t p; asm("ex2.approx.f16x2 %0, %1;" : "=r"(p) : "r"(t)); return p;
}

// ---------------- prep: fp16 convert + norms/rowsums, zero accumulators ----------------
__global__ void prep_kernel(const float* __restrict__ x, const float* __restrict__ wq,
                            const float* __restrict__ wo){
    int r = blockIdx.x;
    const float* src; __half* dstb; float* dsq; float* drs = nullptr;
    if (r < M_TOT)              { src = x  + (size_t)r*DD; dstb = g_xh  + (size_t)r*DD; dsq = g_xsq + r; }
    else if (r < M_TOT + NQKV)  { int rr = r - M_TOT; src = wq + (size_t)rr*DD; dstb = g_wqh + (size_t)rr*DD; dsq = g_wqsq + rr; }
    else { int rr = r - M_TOT - NQKV; src = wo + (size_t)rr*DD; dstb = g_woh + (size_t)rr*DD; dsq = g_wosq + rr; drs = g_wrs + rr; }

    if (r < 1024) g_qksq[r*128 + threadIdx.x] = 0.f;   // zero 2*32*2048 norm accumulators

    float4 v = ((const float4*)src)[threadIdx.x];
    __half2 h0 = __floats2half2_rn(v.x, v.y);
    __half2 h1 = __floats2half2_rn(v.z, v.w);
    __half2* d2 = (__half2*)(dstb + threadIdx.x*4);
    d2[0]=h0; d2[1]=h1;
    float2 f0 = __half22float2(h0), f1 = __half22float2(h1);
    float ss = f0.x*f0.x + f0.y*f0.y + f1.x*f1.x + f1.y*f1.y;
    float rs = f0.x + f0.y + f1.x + f1.y;
    #pragma unroll
    for (int o=16;o>0;o>>=1){ ss += __shfl_xor_sync(~0u, ss, o); rs += __shfl_xor_sync(~0u, rs, o); }
    __shared__ float wsum[4], wsum2[4];
    if ((threadIdx.x&31)==0){ wsum[threadIdx.x>>5]=ss; wsum2[threadIdx.x>>5]=rs; }
    __syncthreads();
    if (threadIdx.x==0){
        *dsq = wsum[0]+wsum[1]+wsum[2]+wsum[3];
        if (drs) *drs = wsum2[0]+wsum2[1]+wsum2[2]+wsum2[3];
        if (r < M_TOT) g_osq[r] = 0.f;
    }
}

// ===================== GEMMs: CTA 128x128, warp 32x64, K-chunk 32, 3-stage, fp16 acc ================
// stage: A [128][40] half = 10240 B, B [128][40] half = 10240 B -> 20480 B; 3 stages = 60 KB -> 3 CTAs/SM
#define GST 20480
#define GSM_BYTES (3*GST)

// ---------------- QKV GEMM ----------------
__global__ __launch_bounds__(256,3) void qkv_gemm_tc(){
    extern __shared__ char smc[];
    int tid=threadIdx.x, lane=tid&31, wid=tid>>5;
    int wr=wid>>1, wc=wid&1;
    int m0=blockIdx.y*128, n0=blockIdx.x*128;
    uint32_t acc[2][8][2];
    #pragma unroll
    for(int i=0;i<2;i++) for(int j=0;j<8;j++){ acc[i][j][0]=0u; acc[i][j][1]=0u; }

    auto load_stage = [&](int kt, int st){
        __half* As = (__half*)(smc + st*GST);
        __half* Bs = (__half*)(smc + st*GST + 10240);
        #pragma unroll
        for (int u=0;u<2;u++){
            int idx=tid+256*u; int row=idx>>2; int q=idx&3;
            cp_async16(&As[row*40+q*8], &g_xh [(size_t)(m0+row)*DD + kt + q*8]);
            cp_async16(&Bs[row*40+q*8], &g_wqh[(size_t)(n0+row)*DD + kt + q*8]);
        }
    };
    load_stage(0, 0);  CP_COMMIT;
    load_stage(32, 1); CP_COMMIT;

    for (int it=0; it<16; it++){
        int st = it%3;
        if (it<15) cp_wait<1>(); else cp_wait<0>();
        __syncthreads();
        if (it+2 < 16){ load_stage((it+2)*32, (it+2)%3); CP_COMMIT; }
        __half* As = (__half*)(smc + st*GST);
        __half* Bs = (__half*)(smc + st*GST + 10240);
        #pragma unroll
        for (int kc=0;kc<2;kc++){
            uint32_t a[2][4];
            #pragma unroll
            for (int mt=0;mt<2;mt++)
                ldmx4(a[mt][0],a[mt][1],a[mt][2],a[mt][3],
                      &As[(wr*32+mt*16+(lane&15))*40 + kc*16 + (lane>>4)*8]);
            #pragma unroll
            for (int p=0;p<4;p++){
                uint32_t b0,b1,b2,b3;
                ldmx4(b0,b1,b2,b3,
                      &Bs[(wc*64+p*16+(lane>>4)*8+(lane&7))*40 + kc*16 + ((lane>>3)&1)*8]);
                #pragma unroll
                for (int mt=0;mt<2;mt++){
                    mmaf16(acc[mt][2*p],   a[mt], b0,b1);
                    mmaf16(acc[mt][2*p+1], a[mt], b2,b3);
                }
            }
        }
    }
    int colbase = n0 + wc*64;
    int part = colbase>>9, rem = colbase&511, h = rem>>6, dbase = rem&63;
    #pragma unroll
    for (int mt=0;mt<2;mt++){
        #pragma unroll
        for (int hh=0;hh<2;hh++){
            int m = m0 + wr*32 + mt*16 + (lane>>2) + 8*hh;
            int b = m>>11, n = m&2047;
            float xs = g_xsq[m];
            __half* orow = g_qkvh + ((size_t)(part*32 + b*8 + h)*NN + n)*DH;
            float ss = 0.f;
            #pragma unroll
            for (int nt=0;nt<8;nt++){
                int col = colbase + nt*8 + 2*(lane&3);
                float2 dd = __half22float2(*(__half2*)&acc[mt][nt][hh]);
                float v0 = sqrtf(fmaxf(xs + g_wqsq[col]   - 2.f*dd.x, 0.f)) - 32.f;
                float v1 = sqrtf(fmaxf(xs + g_wqsq[col+1] - 2.f*dd.y, 0.f)) - 32.f;
                __half2 h2 = __floats2half2_rn(v0, v1);
                *(__half2*)&orow[dbase + nt*8 + 2*(lane&3)] = h2;
                float2 rr = __half22float2(h2);           // norms from ROUNDED values
                ss += rr.x*rr.x + rr.y*rr.y;
            }
            if (part < 2){                                // q- AND k-norms
                ss += __shfl_xor_sync(~0u, ss, 1);
                ss += __shfl_xor_sync(~0u, ss, 2);
                if ((lane&3)==0) atomicAdd(&g_qksq[(part*32 + b*8 + h)*NN + n], ss);
            }
        }
    }
}

// ---------------- output GEMM ----------------
__global__ __launch_bounds__(256,3) void out_gemm_tc(float* __restrict__ out){
    extern __shared__ char smc[];
    int tid=threadIdx.x, lane=tid&31, wid=tid>>5;
    int wr=wid>>1, wc=wid&1;
    int m0=blockIdx.y*128, n0=blockIdx.x*128;
    uint32_t acc[2][8][2];
    #pragma unroll
    for(int i=0;i<2;i++) for(int j=0;j<8;j++){ acc[i][j][0]=0u; acc[i][j][1]=0u; }

    auto load_stage = [&](int kt, int st){
        __half* As = (__half*)(smc + st*GST);
        __half* Bs = (__half*)(smc + st*GST + 10240);
        #pragma unroll
        for (int u=0;u<2;u++){
            int idx=tid+256*u; int row=idx>>2; int q=idx&3;
            cp_async16(&As[row*40+q*8], &g_oh [(size_t)(m0+row)*DD + kt + q*8]);
            cp_async16(&Bs[row*40+q*8], &g_woh[(size_t)(n0+row)*DD + kt + q*8]);
        }
    };
    load_stage(0, 0);  CP_COMMIT;
    load_stage(32, 1); CP_COMMIT;

    for (int it=0; it<16; it++){
        int st = it%3;
        if (it<15) cp_wait<1>(); else cp_wait<0>();
        __syncthreads();
        if (it+2 < 16){ load_stage((it+2)*32, (it+2)%3); CP_COMMIT; }
        __half* As = (__half*)(smc + st*GST);
        __half* Bs = (__half*)(smc + st*GST + 10240);
        #pragma unroll
        for (int kc=0;kc<2;kc++){
            uint32_t a[2][4];
            #pragma unroll
            for (int mt=0;mt<2;mt++)
                ldmx4(a[mt][0],a[mt][1],a[mt][2],a[mt][3],
                      &As[(wr*32+mt*16+(lane&15))*40 + kc*16 + (lane>>4)*8]);
            #pragma unroll
            for (int p=0;p<4;p++){
                uint32_t b0,b1,b2,b3;
                ldmx4(b0,b1,b2,b3,
                      &Bs[(wc*64+p*16+(lane>>4)*8+(lane&7))*40 + kc*16 + ((lane>>3)&1)*8]);
                #pragma unroll
                for (int mt=0;mt<2;mt++){
                    mmaf16(acc[mt][2*p],   a[mt], b0,b1);
                    mmaf16(acc[mt][2*p+1], a[mt], b2,b3);
                }
            }
        }
    }
    #pragma unroll
    for (int mt=0;mt<2;mt++){
        #pragma unroll
        for (int hh=0;hh<2;hh++){
            int m = m0 + wr*32 + mt*16 + (lane>>2) + 8*hh;
            float os = g_osq[m];
            #pragma unroll
            for (int nt=0;nt<8;nt++){
                int col = n0 + wc*64 + nt*8 + 2*(lane&3);
                float2 dd = __half22float2(*(__half2*)&acc[mt][nt][hh]);
                float dot0 = dd.x + 32.f*g_wrs[col];
                float dot1 = dd.y + 32.f*g_wrs[col+1];
                out[(size_t)m*DD + col]   = sqrtf(fmaxf(os + g_wosq[col]   - 2.f*dot0, 0.f));
                out[(size_t)m*DD + col+1] = sqrtf(fmaxf(os + g_wosq[col+1] - 2.f*dot1, 0.f));
            }
        }
    }
}

// ---------------- flash attention: fp16 end-to-end, bounded exponent, 3-stage ring, 3 CTAs/SM ------
// smem: Qs [128][72] = 18432 | stage s at 18432+s*18688: K(9216) V(9216) ksq(256)
#define FSTAGE 18688
#define FSM_BYTES (18432 + 3*FSTAGE)
__global__ __launch_bounds__(256,3) void flash_tc(){
    extern __shared__ char smem[];
    __half* Qs = (__half*)smem;

    int tid=threadIdx.x, lane=tid&31, w=tid>>5;
    int bh = blockIdx.y; int i0 = blockIdx.x*128;
    const __half* qg = g_qkvh + ((size_t)(0*32+bh)*NN + i0)*DH;
    const __half* kg = g_qkvh + (size_t)(1*32+bh)*NN*DH;
    const __half* vg = g_qkvh + (size_t)(2*32+bh)*NN*DH;
    const float* qsqg = g_qksq + (size_t)(0*32+bh)*NN + i0;
    const float* ksqg = g_qksq + (size_t)(1*32+bh)*NN;

    auto load_stage = [&](int j0, int st){
        char* base = smem + 18432 + st*FSTAGE;
        __half* Ks = (__half*)base;
        __half* Vs = (__half*)(base + 9216);
        float* kq = (float*)(base + 18432);
        #pragma unroll
        for (int u=0;u<2;u++){
            int idx=tid+256*u; int row=idx>>3; int q=idx&7;
            cp_async16(&Ks[row*72+q*8], &kg[(size_t)(j0+row)*DH+q*8]);
            cp_async16(&Vs[row*72+q*8], &vg[(size_t)(j0+row)*DH+q*8]);
        }
        if (tid<16) cp_async16(&kq[tid*4], &ksqg[j0+tid*4]);
    };

    #pragma unroll
    for (int u=0;u<4;u++){
        int idx=tid+256*u; int row=idx>>3; int q=idx&7;
        cp_async16(&Qs[row*72+q*8], &qg[(size_t)row*DH + q*8]);
    }
    CP_COMMIT;
    load_stage(0, 0);  CP_COMMIT;
    load_stage(64, 1); CP_COMMIT;

    cp_wait<2>();
    __syncthreads();

    uint32_t qf[4][4];
    #pragma unroll
    for (int kc=0;kc<4;kc++)
        ldmx4(qf[kc][0],qf[kc][1],qf[kc][2],qf[kc][3],
              &Qs[(w*16+(lane&15))*72 + kc*16 + (lane>>4)*8]);

    const float C2 = 0.125f*LOG2E;
    const float BIAS = 12.0f;                 // logit = BIAS - C2*d^2 <= BIAS -> p <= 4096 (fp16-safe)
    const __half2 C1h = __float2half2_rn(0.25f*LOG2E);
    float rowc0 = BIAS - C2*qsqg[w*16 + (lane>>2)];
    float rowc1 = BIAS - C2*qsqg[w*16 + (lane>>2) + 8];

    float lr[2] = {0.f, 0.f};
    uint32_t accO[8][2];
    #pragma unroll
    for (int j=0;j<8;j++){ accO[j][0]=0u; accO[j][1]=0u; }

    for (int t=0; t<32; t++){
        int st = t%3;
        if (t<31) cp_wait<1>(); else cp_wait<0>();
        __syncthreads();
        if (t+2 < 32){ load_stage((t+2)*64, (t+2)%3); CP_COMMIT; }
        char* base = smem + 18432 + st*FSTAGE;
        __half* Ks = (__half*)base;
        __half* Vs = (__half*)(base + 9216);
        const float* ksq = (const float*)(base + 18432);

        // S = Q.K^T (fp16 accum): 16 rows x 64 j per warp
        uint32_t s2[8][2];
        #pragma unroll
        for(int j=0;j<8;j++){ s2[j][0]=0u; s2[j][1]=0u; }
        #pragma unroll
        for (int kc=0;kc<4;kc++){
            #pragma unroll
            for (int p=0;p<4;p++){
                uint32_t b0,b1,b2,b3;
                ldmx4(b0,b1,b2,b3,
                      &Ks[(p*16+(lane>>4)*8+(lane&7))*72 + kc*16 + ((lane>>3)&1)*8]);
                mmaf16(s2[2*p],   qf[kc], b0,b1);
                mmaf16(s2[2*p+1], qf[kc], b2,b3);
            }
        }

        // p = exp2(C1*s + rowc - C2*|k|^2) in half2; result IS the PV A-fragment
        __half2 hs0 = __float2half2_rn(0.f), hs1 = __float2half2_rn(0.f);
        #pragma unroll
        for (int nt=0;nt<8;nt++){
            float2 kf = *(const float2*)&ksq[nt*8 + 2*(lane&3)];
            __half2 c0 = __floats2half2_rn(rowc0 - C2*kf.x, rowc0 - C2*kf.y);
            __half2 c1 = __floats2half2_rn(rowc1 - C2*kf.x, rowc1 - C2*kf.y);
            __half2 t0 = __hfma2(*(__half2*)&s2[nt][0], C1h, c0);
            __half2 t1 = __hfma2(*(__half2*)&s2[nt][1], C1h, c1);
            s2[nt][0] = h2exp2(*(uint32_t*)&t0);
            s2[nt][1] = h2exp2(*(uint32_t*)&t1);
            hs0 = __hadd2(hs0, *(__half2*)&s2[nt][0]);
            hs1 = __hadd2(hs1, *(__half2*)&s2[nt][1]);
        }
        {
            float2 f0 = __half22float2(hs0), f1 = __half22float2(hs1);
            float rs0 = f0.x + f0.y, rs1 = f1.x + f1.y;
            rs0 += __shfl_xor_sync(~0u, rs0, 1); rs0 += __shfl_xor_sync(~0u, rs0, 2);
            rs1 += __shfl_xor_sync(~0u, rs1, 1); rs1 += __shfl_xor_sync(~0u, rs1, 2);
            lr[0] += rs0; lr[1] += rs1;
        }

        // O += P.V (fp16 accum), P fragments = s2 directly
        #pragma unroll
        for (int kc=0;kc<4;kc++){
            uint32_t pa[4] = { s2[2*kc][0], s2[2*kc][1], s2[2*kc+1][0], s2[2*kc+1][1] };
            #pragma unroll
            for (int dp=0;dp<4;dp++){
                uint32_t b0,b1,b2,b3;
                ldmx4t(b0,b1,b2,b3,
                       &Vs[(kc*16+((lane>>3)&1)*8+(lane&7))*72 + dp*16 + (lane>>4)*8]);
                mmaf16(accO[2*dp],   pa, b0,b1);
                mmaf16(accO[2*dp+1], pa, b2,b3);
            }
        }
    }

    // epilogue: warp-private rows
    int b = bh>>3, h = bh&7;
    #pragma unroll
    for (int hh=0;hh<2;hh++){
        int row = w*16 + (lane>>2) + 8*hh;
        float inv = 1.f/lr[hh];
        __half* orow = g_oh + (size_t)(b*NN + i0 + row)*DD + h*DH;
        float ss = 0.f;
        #pragma unroll
        for (int nt=0;nt<8;nt++){
            float2 f = __half22float2(*(__half2*)&accO[nt][hh]);
            float o0 = f.x*inv, o1 = f.y*inv;
            __half2 h2 = __floats2half2_rn(o0, o1);
            *(__half2*)&orow[nt*8 + 2*(lane&3)] = h2;
            float2 rr = __half22float2(h2);
            float a0 = rr.x+32.f, a1 = rr.y+32.f;
            ss += a0*a0 + a1*a1;
        }
        ss += __shfl_xor_sync(~0u, ss, 1);
        ss += __shfl_xor_sync(~0u, ss, 2);
        if ((lane&3)==0) atomicAdd(&g_osq[b*NN + i0 + row], ss);
    }
}

// ---------------- launch ----------------
extern "C" void kernel_launch(void* const* d_in, const int* in_sizes, int n_in,
                              void* d_out, int out_size) {
    const float* x    = (const float*)d_in[0];
    const float* wqkv = (const float*)d_in[1];
    const float* wout = (const float*)d_in[2];
    float* out = (float*)d_out;

    cudaFuncSetAttribute(qkv_gemm_tc, cudaFuncAttributeMaxDynamicSharedMemorySize, GSM_BYTES);
    cudaFuncSetAttribute(out_gemm_tc, cudaFuncAttributeMaxDynamicSharedMemorySize, GSM_BYTES);
    cudaFuncSetAttribute(flash_tc,    cudaFuncAttributeMaxDynamicSharedMemorySize, FSM_BYTES);

    prep_kernel<<<M_TOT + NQKV + DD, 128>>>(x, wqkv, wout);
    qkv_gemm_tc<<<dim3(NQKV/128, M_TOT/128), 256, GSM_BYTES>>>();
    flash_tc<<<dim3(NN/128, 32), 256, FSM_BYTES>>>();
    out_gemm_tc<<<dim3(DD/128, M_TOT/128), 256, GSM_BYTES>>>(out);
}